// round 14
// baseline (speedup 1.0000x reference)
#include <cuda_runtime.h>
#include <cuda_bf16.h>
#include <cuda_fp16.h>
#include <cstdint>

// ---------------------------------------------------------------------------
// Problem constants
// ---------------------------------------------------------------------------
constexpr int Bc  = 2;
constexpr int Sc  = 2048;
constexpr int Dc  = 1024;
constexpr int Hc  = 16;
constexpr int DHc = 64;
constexpr int FFc = 4096;
constexpr int BS  = Bc * Sc;
constexpr float LN_EPS = 1e-5f;

// ---------------------------------------------------------------------------
// Scratch (device globals; allocation is forbidden)
// ---------------------------------------------------------------------------
__device__ float g_vp[BS * Dc];
__device__ float g_zd[BS * Dc];
__device__ float g_x [BS * Dc];

__device__ __nv_bfloat16 g_qih[BS*Dc], g_qil[BS*Dc];
__device__ __nv_bfloat16 g_kih[BS*Dc], g_kil[BS*Dc];
__device__ __nv_bfloat16 g_vih[BS*Dc], g_vil[BS*Dc];
__device__ __nv_bfloat16 g_wqh[Dc*Dc], g_wql[Dc*Dc];
__device__ __nv_bfloat16 g_wkh[Dc*Dc], g_wkl[Dc*Dc];
__device__ __nv_bfloat16 g_wvh[Dc*Dc], g_wvl[Dc*Dc];
__device__ __nv_bfloat16 g_wdh[Dc*Dc], g_wdl[Dc*Dc];
__device__ __nv_bfloat16 g_qph[BS*Dc], g_qpl[BS*Dc];
__device__ __nv_bfloat16 g_kph[BS*Dc], g_kpl[BS*Dc];
__device__ __nv_bfloat16 g_vth[BS*Dc], g_vtl[BS*Dc];                     // [B, D, S]
__device__ __nv_bfloat16 g_zh[BS*Dc], g_zl[BS*Dc];
__device__ __nv_bfloat16 g_maskb[(size_t)Sc*Sc];                         // bf16 mask

// fp16 FFN path
__device__ __half g_w1h16[(size_t)FFc*Dc];                               // [4096,1024] K-major
__device__ __half g_w2h16[(size_t)Dc*FFc];                               // [1024,4096] K-major
__device__ __half g_xh16[BS*Dc], g_xl16[BS*Dc];
__device__ __half g_f1h16[(size_t)BS*FFc], g_f1l16[(size_t)BS*FFc];

// ---------------------------------------------------------------------------
// PTX helpers (legal on plain compute_103)
// ---------------------------------------------------------------------------
__device__ __forceinline__ uint32_t s2u(const void* p) {
    uint32_t a;
    asm("{ .reg .u64 t; cvta.to.shared.u64 t, %1; cvt.u32.u64 %0, t; }" : "=r"(a) : "l"(p));
    return a;
}
#define SWZ(x) ((x) ^ (((x) >> 3) & 0x70))
#define CPA16(dst, src) asm volatile("cp.async.cg.shared.global [%0], [%1], 16;" :: "r"(dst), "l"(src))
#define CPA_COMMIT()    asm volatile("cp.async.commit_group;" ::: "memory")
#define CPA_WAIT(n)     asm volatile("cp.async.wait_group %0;" :: "n"(n) : "memory")

__device__ __forceinline__ void ldsm4(uint32_t* r, uint32_t addr) {
    asm volatile("ldmatrix.sync.aligned.m8n8.x4.shared.b16 {%0,%1,%2,%3}, [%4];"
        : "=r"(r[0]), "=r"(r[1]), "=r"(r[2]), "=r"(r[3]) : "r"(addr));
}
__device__ __forceinline__ void mma16816(float* c, const uint32_t* a, const uint32_t* b) {
    asm volatile("mma.sync.aligned.m16n8k16.row.col.f32.bf16.bf16.f32 "
        "{%0,%1,%2,%3}, {%4,%5,%6,%7}, {%8,%9}, {%0,%1,%2,%3};"
        : "+f"(c[0]), "+f"(c[1]), "+f"(c[2]), "+f"(c[3])
        : "r"(a[0]), "r"(a[1]), "r"(a[2]), "r"(a[3]), "r"(b[0]), "r"(b[1]));
}
__device__ __forceinline__ void mma16816h(float* c, const uint32_t* a, const uint32_t* b) {
    asm volatile("mma.sync.aligned.m16n8k16.row.col.f32.f16.f16.f32 "
        "{%0,%1,%2,%3}, {%4,%5,%6,%7}, {%8,%9}, {%0,%1,%2,%3};"
        : "+f"(c[0]), "+f"(c[1]), "+f"(c[2]), "+f"(c[3])
        : "r"(a[0]), "r"(a[1]), "r"(a[2]), "r"(a[3]), "r"(b[0]), "r"(b[1]));
}
__device__ __forceinline__ uint32_t packbf2(float lo, float hi) {
    uint32_t r;
    asm("cvt.rn.bf16x2.f32 %0, %1, %2;" : "=r"(r) : "f"(hi), "f"(lo));
    return r;
}
__device__ __forceinline__ uint32_t packh2(float lo, float hi) {
    uint32_t r;
    asm("cvt.rn.f16x2.f32 %0, %1, %2;" : "=r"(r) : "f"(hi), "f"(lo));
    return r;
}
__device__ __forceinline__ float bf_round(float x) {
    return __bfloat162float(__float2bfloat16(x));
}
__device__ __forceinline__ float h_round(float x) {
    return __half2float(__float2half_rn(x));
}

// ---------------------------------------------------------------------------
// bf16 HMMA GEMM (3-term): C[M,N] = (Ah+Al)[M,K] @ (Bh+Bl)^T, B [N,K] K-major
// EPI: 0 fp32, 1 bias fp32, 4 bf16split, 5 scale0.125+bf16split
// ---------------------------------------------------------------------------
template <int BN, int EPI>
__global__ void __launch_bounds__(256)
hmma_gemm(const __nv_bfloat16* __restrict__ Ah_, const __nv_bfloat16* __restrict__ Al_, int lda,
          const __nv_bfloat16* __restrict__ Bh_, const __nv_bfloat16* __restrict__ Bl_, int ldb,
          float* __restrict__ C_, __nv_bfloat16* __restrict__ Ch_, __nv_bfloat16* __restrict__ Cl_,
          int ldc, int K, const float* __restrict__ bias)
{
    constexpr int NF    = BN / 32;
    constexpr int AOFF  = 16384;
    constexpr int BOFF  = 32768;
    constexpr int BPART = BN * 128;
    constexpr int STAGE = BOFF + 2 * BPART;

    extern __shared__ __align__(1024) char smem[];
    const uint32_t sbase = s2u(smem);

    const int tid  = threadIdx.x;
    const int wid  = tid >> 5;
    const int lane = tid & 31;
    const int warp_m = wid & 1;
    const int warp_n = wid >> 1;

    const int m0 = blockIdx.y * 128;
    const int n0 = blockIdx.x * BN;
    const int NC = K >> 6;

    float acc[4][NF][4];
    #pragma unroll
    for (int i = 0; i < 4; i++)
        #pragma unroll
        for (int j = 0; j < NF; j++)
            #pragma unroll
            for (int e = 0; e < 4; e++) acc[i][j][e] = 0.f;

    auto load_chunk = [&](int c, int s) {
        const uint32_t s0 = sbase + s * STAGE;
        const int kk = c * 64;
        #pragma unroll
        for (int i = 0; i < 4; i++) {
            const int e = tid + i * 256;
            const int row = e >> 3, c16 = e & 7;
            const uint32_t off = SWZ(row * 128 + c16 * 16);
            const size_t go = (size_t)(m0 + row) * lda + kk + c16 * 8;
            CPA16(s0 + off,        Ah_ + go);
            CPA16(s0 + AOFF + off, Al_ + go);
        }
        #pragma unroll
        for (int i = 0; i < BN / 32; i++) {
            const int e = tid + i * 256;
            const int row = e >> 3, c16 = e & 7;
            const uint32_t off = SWZ(row * 128 + c16 * 16);
            const size_t go = (size_t)(n0 + row) * ldb + kk + c16 * 8;
            CPA16(s0 + BOFF + off,         Bh_ + go);
            CPA16(s0 + BOFF + BPART + off, Bl_ + go);
        }
    };

    load_chunk(0, 0); CPA_COMMIT();
    if (NC > 1) { load_chunk(1, 1); CPA_COMMIT(); }

    const int a_r = lane & 15;
    const int a_k = (lane >> 4) & 1;
    const int b_r = lane & 7;
    const int b_k = (lane >> 3) & 1;
    const int b_n = (lane >> 4) & 1;

    for (int c = 0; c < NC; c++) {
        if (c + 1 < NC) { CPA_WAIT(1); } else { CPA_WAIT(0); }
        __syncthreads();
        const uint32_t s0 = sbase + (c & 1) * STAGE;

        #pragma unroll
        for (int ks = 0; ks < 4; ks++) {
            uint32_t ah[4][4], al[4][4];
            #pragma unroll
            for (int im = 0; im < 4; im++) {
                const uint32_t off = SWZ((warp_m * 64 + im * 16 + a_r) * 128 + ks * 32 + a_k * 16);
                ldsm4(ah[im], s0 + off);
                ldsm4(al[im], s0 + AOFF + off);
            }
            uint32_t bh[NF * 2], bl[NF * 2];
            #pragma unroll
            for (int j2 = 0; j2 < NF / 2; j2++) {
                const uint32_t off = SWZ((warp_n * (BN / 4) + j2 * 16 + b_n * 8 + b_r) * 128 + ks * 32 + b_k * 16);
                ldsm4(&bh[j2 * 4], s0 + BOFF + off);
                ldsm4(&bl[j2 * 4], s0 + BOFF + BPART + off);
            }
            #pragma unroll
            for (int im = 0; im < 4; im++)
                #pragma unroll
                for (int jn = 0; jn < NF; jn++) {
                    mma16816(acc[im][jn], ah[im], &bh[jn * 2]);
                    mma16816(acc[im][jn], ah[im], &bl[jn * 2]);
                    mma16816(acc[im][jn], al[im], &bh[jn * 2]);
                }
        }
        __syncthreads();
        if (c + 2 < NC) { load_chunk(c + 2, c & 1); CPA_COMMIT(); }
    }

    const int qr = lane >> 2;
    const int qc = (lane & 3) * 2;
    #pragma unroll
    for (int im = 0; im < 4; im++) {
        const int m = m0 + warp_m * 64 + im * 16 + qr;
        #pragma unroll
        for (int jn = 0; jn < NF; jn++) {
            const int n = n0 + warp_n * (BN / 4) + jn * 8 + qc;
            float2 v0 = make_float2(acc[im][jn][0], acc[im][jn][1]);
            float2 v1 = make_float2(acc[im][jn][2], acc[im][jn][3]);
            if (EPI == 1) {
                const float2 bv = *reinterpret_cast<const float2*>(bias + n);
                v0.x += bv.x; v0.y += bv.y; v1.x += bv.x; v1.y += bv.y;
            }
            if (EPI == 5) {
                v0.x *= 0.125f; v0.y *= 0.125f; v1.x *= 0.125f; v1.y *= 0.125f;
            }
            if (EPI == 4 || EPI == 5) {
                *reinterpret_cast<uint32_t*>(Ch_ + (size_t)m * ldc + n)       = packbf2(v0.x, v0.y);
                *reinterpret_cast<uint32_t*>(Ch_ + (size_t)(m + 8) * ldc + n) = packbf2(v1.x, v1.y);
                *reinterpret_cast<uint32_t*>(Cl_ + (size_t)m * ldc + n)       =
                    packbf2(v0.x - bf_round(v0.x), v0.y - bf_round(v0.y));
                *reinterpret_cast<uint32_t*>(Cl_ + (size_t)(m + 8) * ldc + n) =
                    packbf2(v1.x - bf_round(v1.x), v1.y - bf_round(v1.y));
            } else {
                *reinterpret_cast<float2*>(C_ + (size_t)m * ldc + n)       = v0;
                *reinterpret_cast<float2*>(C_ + (size_t)(m + 8) * ldc + n) = v1;
            }
        }
    }
}

// ---------------------------------------------------------------------------
// fp16 HMMA GEMM (2-term): C[M,N] = (Ah+Al)[M,K] @ B^T, B [N,K] K-major fp16.
// BN=128. Stage = Ah 16K + Al 16K + B 16K = 48K; 2 stages = 96K -> 2 CTAs/SM.
// EPI: 1 bias fp32, 2 bias+relu+fp16split
// ---------------------------------------------------------------------------
template <int EPI>
__global__ void __launch_bounds__(256, 2)
hmma_gemm_h(const __half* __restrict__ Ah_, const __half* __restrict__ Al_, int lda,
            const __half* __restrict__ B_, int ldb,
            float* __restrict__ C_, __half* __restrict__ Ch_, __half* __restrict__ Cl_,
            int ldc, int K, const float* __restrict__ bias)
{
    constexpr int AOFF  = 16384;
    constexpr int BOFF  = 32768;
    constexpr int STAGE = 49152;

    extern __shared__ __align__(1024) char smem[];
    const uint32_t sbase = s2u(smem);

    const int tid  = threadIdx.x;
    const int wid  = tid >> 5;
    const int lane = tid & 31;
    const int warp_m = wid & 1;
    const int warp_n = wid >> 1;

    const int m0 = blockIdx.y * 128;
    const int n0 = blockIdx.x * 128;
    const int NC = K >> 6;

    float acc[4][4][4];
    #pragma unroll
    for (int i = 0; i < 4; i++)
        #pragma unroll
        for (int j = 0; j < 4; j++)
            #pragma unroll
            for (int e = 0; e < 4; e++) acc[i][j][e] = 0.f;

    auto load_chunk = [&](int c, int s) {
        const uint32_t s0 = sbase + s * STAGE;
        const int kk = c * 64;
        #pragma unroll
        for (int i = 0; i < 4; i++) {
            const int e = tid + i * 256;
            const int row = e >> 3, c16 = e & 7;
            const uint32_t off = SWZ(row * 128 + c16 * 16);
            const size_t go = (size_t)(m0 + row) * lda + kk + c16 * 8;
            CPA16(s0 + off,        Ah_ + go);
            CPA16(s0 + AOFF + off, Al_ + go);
        }
        #pragma unroll
        for (int i = 0; i < 4; i++) {
            const int e = tid + i * 256;
            const int row = e >> 3, c16 = e & 7;
            const uint32_t off = SWZ(row * 128 + c16 * 16);
            CPA16(s0 + BOFF + off, B_ + (size_t)(n0 + row) * ldb + kk + c16 * 8);
        }
    };

    load_chunk(0, 0); CPA_COMMIT();
    if (NC > 1) { load_chunk(1, 1); CPA_COMMIT(); }

    const int a_r = lane & 15;
    const int a_k = (lane >> 4) & 1;
    const int b_r = lane & 7;
    const int b_k = (lane >> 3) & 1;
    const int b_n = (lane >> 4) & 1;

    for (int c = 0; c < NC; c++) {
        if (c + 1 < NC) { CPA_WAIT(1); } else { CPA_WAIT(0); }
        __syncthreads();
        const uint32_t s0 = sbase + (c & 1) * STAGE;

        #pragma unroll
        for (int ks = 0; ks < 4; ks++) {
            uint32_t bh[8];
            #pragma unroll
            for (int j2 = 0; j2 < 2; j2++) {
                const uint32_t off = SWZ((warp_n * 32 + j2 * 16 + b_n * 8 + b_r) * 128 + ks * 32 + b_k * 16);
                ldsm4(&bh[j2 * 4], s0 + BOFF + off);
            }
            #pragma unroll
            for (int im = 0; im < 4; im++) {
                uint32_t ah[4], al[4];
                const uint32_t off = SWZ((warp_m * 64 + im * 16 + a_r) * 128 + ks * 32 + a_k * 16);
                ldsm4(ah, s0 + off);
                ldsm4(al, s0 + AOFF + off);
                #pragma unroll
                for (int jn = 0; jn < 4; jn++) {
                    mma16816h(acc[im][jn], ah, &bh[jn * 2]);
                    mma16816h(acc[im][jn], al, &bh[jn * 2]);
                }
            }
        }
        __syncthreads();
        if (c + 2 < NC) { load_chunk(c + 2, c & 1); CPA_COMMIT(); }
    }

    const int qr = lane >> 2;
    const int qc = (lane & 3) * 2;
    #pragma unroll
    for (int im = 0; im < 4; im++) {
        const int m = m0 + warp_m * 64 + im * 16 + qr;
        #pragma unroll
        for (int jn = 0; jn < 4; jn++) {
            const int n = n0 + warp_n * 32 + jn * 8 + qc;
            float2 v0 = make_float2(acc[im][jn][0], acc[im][jn][1]);
            float2 v1 = make_float2(acc[im][jn][2], acc[im][jn][3]);
            const float2 bv = *reinterpret_cast<const float2*>(bias + n);
            v0.x += bv.x; v0.y += bv.y; v1.x += bv.x; v1.y += bv.y;
            if (EPI == 2) {
                v0.x = fmaxf(v0.x, 0.f); v0.y = fmaxf(v0.y, 0.f);
                v1.x = fmaxf(v1.x, 0.f); v1.y = fmaxf(v1.y, 0.f);
                *reinterpret_cast<uint32_t*>(Ch_ + (size_t)m * ldc + n)       = packh2(v0.x, v0.y);
                *reinterpret_cast<uint32_t*>(Ch_ + (size_t)(m + 8) * ldc + n) = packh2(v1.x, v1.y);
                *reinterpret_cast<uint32_t*>(Cl_ + (size_t)m * ldc + n)       =
                    packh2(v0.x - h_round(v0.x), v0.y - h_round(v0.y));
                *reinterpret_cast<uint32_t*>(Cl_ + (size_t)(m + 8) * ldc + n) =
                    packh2(v1.x - h_round(v1.x), v1.y - h_round(v1.y));
            } else {
                *reinterpret_cast<float2*>(C_ + (size_t)m * ldc + n)       = v0;
                *reinterpret_cast<float2*>(C_ + (size_t)(m + 8) * ldc + n) = v1;
            }
        }
    }
}

// ---------------------------------------------------------------------------
// Fused FlashAttention (Q pre-scaled by 0.125; mask in bf16)
// ---------------------------------------------------------------------------
__global__ void __launch_bounds__(256)
fa_kernel(const __nv_bfloat16* __restrict__ qh_, const __nv_bfloat16* __restrict__ ql_,
          const __nv_bfloat16* __restrict__ kh_, const __nv_bfloat16* __restrict__ kl_,
          const __nv_bfloat16* __restrict__ vth, const __nv_bfloat16* __restrict__ vtl,
          const __nv_bfloat16* __restrict__ maskb,
          __nv_bfloat16* __restrict__ zh, __nv_bfloat16* __restrict__ zl)
{
    constexpr int QH = 0, QL = 16384;
    constexpr int ST0 = 32768, STB = 65536;
    constexpr int KHo = 0, KLo = 16384, VHo = 32768, VLo = 49152;
    constexpr int NT = Sc / 128;

    extern __shared__ __align__(1024) char smem[];
    const uint32_t sbase = s2u(smem);

    const int tid  = threadIdx.x;
    const int wid  = tid >> 5;
    const int lane = tid & 31;

    const int z = blockIdx.y;
    const int b = z >> 4, h = z & 15;
    const int m0 = blockIdx.x * 128;

    const __nv_bfloat16* Qh = qh_ + ((size_t)(b * Sc + m0)) * Dc + h * DHc;
    const __nv_bfloat16* Ql = ql_ + ((size_t)(b * Sc + m0)) * Dc + h * DHc;
    const __nv_bfloat16* Kh = kh_ + (size_t)b * Sc * Dc + h * DHc;
    const __nv_bfloat16* Kl = kl_ + (size_t)b * Sc * Dc + h * DHc;
    const __nv_bfloat16* Vh = vth + ((size_t)b * Dc + h * DHc) * Sc;
    const __nv_bfloat16* Vl = vtl + ((size_t)b * Dc + h * DHc) * Sc;

    #pragma unroll
    for (int i = 0; i < 4; i++) {
        const int e = tid + i * 256;
        const int row = e >> 3, c16 = e & 7;
        const uint32_t off = SWZ(row * 128 + c16 * 16);
        const size_t go = (size_t)row * Dc + c16 * 8;
        CPA16(sbase + QH + off, Qh + go);
        CPA16(sbase + QL + off, Ql + go);
    }
    auto load_kv = [&](int kt, int s) {
        const uint32_t s0 = sbase + ST0 + s * STB;
        #pragma unroll
        for (int i = 0; i < 4; i++) {
            const int e = tid + i * 256;
            const int row = e >> 3, c16 = e & 7;
            const uint32_t off = SWZ(row * 128 + c16 * 16);
            const size_t go = (size_t)(kt * 128 + row) * Dc + c16 * 8;
            CPA16(s0 + KHo + off, Kh + go);
            CPA16(s0 + KLo + off, Kl + go);
        }
        #pragma unroll
        for (int i = 0; i < 4; i++) {
            const int e = tid + i * 256;
            const int row = e >> 4, c16 = e & 15;
            const uint32_t off = SWZ(row * 256 + c16 * 16);
            const size_t go = (size_t)row * Sc + kt * 128 + c16 * 8;
            CPA16(s0 + VHo + off, Vh + go);
            CPA16(s0 + VLo + off, Vl + go);
        }
    };
    load_kv(0, 0); CPA_COMMIT();
    load_kv(1, 1); CPA_COMMIT();

    const int a_r = lane & 15;
    const int a_k = (lane >> 4) & 1;
    const int b_r = lane & 7;
    const int b_k = (lane >> 3) & 1;
    const int b_n = (lane >> 4) & 1;
    const int qr  = lane >> 2;
    const int qc  = (lane & 3) * 2;

    float O[8][4];
    #pragma unroll
    for (int j = 0; j < 8; j++)
        #pragma unroll
        for (int e = 0; e < 4; e++) O[j][e] = 0.f;
    float pm0 = -1e30f, pm1 = -1e30f, l0 = 0.f, l1 = 0.f;

    const int row0 = m0 + wid * 16 + qr;
    const __nv_bfloat16* mrow0 = maskb + (size_t)row0 * Sc;
    const __nv_bfloat16* mrow1 = maskb + (size_t)(row0 + 8) * Sc;

    for (int kt = 0; kt < NT; kt++) {
        if (kt + 1 < NT) { CPA_WAIT(1); } else { CPA_WAIT(0); }
        __syncthreads();
        const uint32_t s0 = sbase + ST0 + (kt & 1) * STB;

        float s[16][4];
        #pragma unroll
        for (int j = 0; j < 16; j++)
            #pragma unroll
            for (int e = 0; e < 4; e++) s[j][e] = 0.f;

        #pragma unroll
        for (int ks = 0; ks < 4; ks++) {
            uint32_t ah[4], al[4];
            {
                const uint32_t off = SWZ((wid * 16 + a_r) * 128 + ks * 32 + a_k * 16);
                ldsm4(ah, sbase + QH + off);
                ldsm4(al, sbase + QL + off);
            }
            #pragma unroll
            for (int j2 = 0; j2 < 8; j2++) {
                uint32_t bh[4], bl[4];
                const uint32_t off = SWZ((j2 * 16 + b_n * 8 + b_r) * 128 + ks * 32 + b_k * 16);
                ldsm4(bh, s0 + KHo + off);
                ldsm4(bl, s0 + KLo + off);
                mma16816(s[j2 * 2],     ah, bh);
                mma16816(s[j2 * 2],     ah, bl);
                mma16816(s[j2 * 2],     al, bh);
                mma16816(s[j2 * 2 + 1], ah, bh + 2);
                mma16816(s[j2 * 2 + 1], ah, bl + 2);
                mma16816(s[j2 * 2 + 1], al, bh + 2);
            }
        }

        float mx0 = -1e30f, mx1 = -1e30f;
        #pragma unroll
        for (int jn = 0; jn < 16; jn++) {
            const int col = kt * 128 + jn * 8 + qc;
            const float2 mv0 = __bfloat1622float2(
                *reinterpret_cast<const __nv_bfloat162*>(mrow0 + col));
            const float2 mv1 = __bfloat1622float2(
                *reinterpret_cast<const __nv_bfloat162*>(mrow1 + col));
            s[jn][0] += mv0.x;
            s[jn][1] += mv0.y;
            s[jn][2] += mv1.x;
            s[jn][3] += mv1.y;
            mx0 = fmaxf(mx0, fmaxf(s[jn][0], s[jn][1]));
            mx1 = fmaxf(mx1, fmaxf(s[jn][2], s[jn][3]));
        }
        mx0 = fmaxf(mx0, __shfl_xor_sync(0xffffffffu, mx0, 1));
        mx0 = fmaxf(mx0, __shfl_xor_sync(0xffffffffu, mx0, 2));
        mx1 = fmaxf(mx1, __shfl_xor_sync(0xffffffffu, mx1, 1));
        mx1 = fmaxf(mx1, __shfl_xor_sync(0xffffffffu, mx1, 2));
        const float nm0 = fmaxf(pm0, mx0), nm1 = fmaxf(pm1, mx1);
        const float sc0 = __expf(pm0 - nm0), sc1 = __expf(pm1 - nm1);
        l0 *= sc0; l1 *= sc1;
        #pragma unroll
        for (int j = 0; j < 8; j++) {
            O[j][0] *= sc0; O[j][1] *= sc0; O[j][2] *= sc1; O[j][3] *= sc1;
        }
        float sum0 = 0.f, sum1 = 0.f;
        #pragma unroll
        for (int jn = 0; jn < 16; jn++) {
            s[jn][0] = __expf(s[jn][0] - nm0);
            s[jn][1] = __expf(s[jn][1] - nm0);
            s[jn][2] = __expf(s[jn][2] - nm1);
            s[jn][3] = __expf(s[jn][3] - nm1);
            sum0 += s[jn][0] + s[jn][1];
            sum1 += s[jn][2] + s[jn][3];
        }
        sum0 += __shfl_xor_sync(0xffffffffu, sum0, 1);
        sum0 += __shfl_xor_sync(0xffffffffu, sum0, 2);
        sum1 += __shfl_xor_sync(0xffffffffu, sum1, 1);
        sum1 += __shfl_xor_sync(0xffffffffu, sum1, 2);
        l0 += sum0; l1 += sum1;
        pm0 = nm0; pm1 = nm1;

        #pragma unroll
        for (int ks2 = 0; ks2 < 8; ks2++) {
            uint32_t ph[4], pl[4];
            {
                const float p00 = s[2 * ks2][0],     p01 = s[2 * ks2][1];
                const float p10 = s[2 * ks2][2],     p11 = s[2 * ks2][3];
                const float p20 = s[2 * ks2 + 1][0], p21 = s[2 * ks2 + 1][1];
                const float p30 = s[2 * ks2 + 1][2], p31 = s[2 * ks2 + 1][3];
                ph[0] = packbf2(p00, p01);
                ph[1] = packbf2(p10, p11);
                ph[2] = packbf2(p20, p21);
                ph[3] = packbf2(p30, p31);
                pl[0] = packbf2(p00 - bf_round(p00), p01 - bf_round(p01));
                pl[1] = packbf2(p10 - bf_round(p10), p11 - bf_round(p11));
                pl[2] = packbf2(p20 - bf_round(p20), p21 - bf_round(p21));
                pl[3] = packbf2(p30 - bf_round(p30), p31 - bf_round(p31));
            }
            #pragma unroll
            for (int j2 = 0; j2 < 4; j2++) {
                uint32_t vh2[4], vl2[4];
                const uint32_t off = SWZ((j2 * 16 + b_n * 8 + b_r) * 256 + ks2 * 32 + b_k * 16);
                ldsm4(vh2, s0 + VHo + off);
                ldsm4(vl2, s0 + VLo + off);
                mma16816(O[j2 * 2],     ph, vh2);
                mma16816(O[j2 * 2],     ph, vl2);
                mma16816(O[j2 * 2],     pl, vh2);
                mma16816(O[j2 * 2 + 1], ph, vh2 + 2);
                mma16816(O[j2 * 2 + 1], ph, vl2 + 2);
                mma16816(O[j2 * 2 + 1], pl, vh2 + 2);
            }
        }

        __syncthreads();
        if (kt + 2 < NT) { load_kv(kt + 2, kt & 1); CPA_COMMIT(); }
    }

    const float inv0 = 1.0f / l0, inv1 = 1.0f / l1;
    const size_t r0 = (size_t)(b * Sc + row0) * Dc + h * DHc;
    const size_t r1 = r0 + 8 * Dc;
    #pragma unroll
    for (int jn = 0; jn < 8; jn++) {
        const int n = jn * 8 + qc;
        const float a = O[jn][0] * inv0, bb = O[jn][1] * inv0;
        const float c = O[jn][2] * inv1, d  = O[jn][3] * inv1;
        *reinterpret_cast<uint32_t*>(zh + r0 + n) = packbf2(a, bb);
        *reinterpret_cast<uint32_t*>(zl + r0 + n) = packbf2(a - bf_round(a), bb - bf_round(bb));
        *reinterpret_cast<uint32_t*>(zh + r1 + n) = packbf2(c, d);
        *reinterpret_cast<uint32_t*>(zl + r1 + n) = packbf2(c - bf_round(c), d - bf_round(d));
    }
}

// ---------------------------------------------------------------------------
// Elementwise helpers
// ---------------------------------------------------------------------------
__global__ void __launch_bounds__(256)
split_kernel(const float* __restrict__ x, __nv_bfloat16* __restrict__ h,
             __nv_bfloat16* __restrict__ l, long long n)
{
    const long long i = ((long long)blockIdx.x * 256 + threadIdx.x) * 4;
    if (i >= n) return;
    const float4 v = *reinterpret_cast<const float4*>(x + i);
    uint32_t* hp = reinterpret_cast<uint32_t*>(h + i);
    uint32_t* lp = reinterpret_cast<uint32_t*>(l + i);
    hp[0] = packbf2(v.x, v.y); hp[1] = packbf2(v.z, v.w);
    lp[0] = packbf2(v.x - bf_round(v.x), v.y - bf_round(v.y));
    lp[1] = packbf2(v.z - bf_round(v.z), v.w - bf_round(v.w));
}

__global__ void __launch_bounds__(256)
maskbf_kernel(const float* __restrict__ m, __nv_bfloat16* __restrict__ o, long long n)
{
    const long long i = ((long long)blockIdx.x * 256 + threadIdx.x) * 4;
    if (i >= n) return;
    const float4 v = *reinterpret_cast<const float4*>(m + i);
    uint32_t* op = reinterpret_cast<uint32_t*>(o + i);
    op[0] = packbf2(v.x, v.y); op[1] = packbf2(v.z, v.w);
}

__global__ void __launch_bounds__(256)
tsplit_kernel(const float* __restrict__ in, __nv_bfloat16* __restrict__ oh,
              __nv_bfloat16* __restrict__ ol, int R, int Ccols,
              long long inz, long long outz)
{
    __shared__ float t[32][33];
    in += (size_t)blockIdx.z * inz;
    oh += (size_t)blockIdx.z * outz;
    ol += (size_t)blockIdx.z * outz;
    const int c0 = blockIdx.x * 32, r0 = blockIdx.y * 32;
    const int tx = threadIdx.x & 31, ty = threadIdx.x >> 5;
    #pragma unroll
    for (int i = 0; i < 32; i += 8)
        t[ty + i][tx] = in[(size_t)(r0 + ty + i) * Ccols + c0 + tx];
    __syncthreads();
    #pragma unroll
    for (int i = 0; i < 32; i += 8) {
        const float v = t[tx][ty + i];
        const __nv_bfloat16 hb = __float2bfloat16(v);
        const size_t o = (size_t)(c0 + ty + i) * R + r0 + tx;
        oh[o] = hb;
        ol[o] = __float2bfloat16(v - __bfloat162float(hb));
    }
}

// transpose fp32 [R, C] -> fp16 [C, R] single-precision-hi only (weights)
__global__ void __launch_bounds__(256)
tsplit_h_kernel(const float* __restrict__ in, __half* __restrict__ oh, int R, int Ccols)
{
    __shared__ float t[32][33];
    const int c0 = blockIdx.x * 32, r0 = blockIdx.y * 32;
    const int tx = threadIdx.x & 31, ty = threadIdx.x >> 5;
    #pragma unroll
    for (int i = 0; i < 32; i += 8)
        t[ty + i][tx] = in[(size_t)(r0 + ty + i) * Ccols + c0 + tx];
    __syncthreads();
    #pragma unroll
    for (int i = 0; i < 32; i += 8)
        oh[(size_t)(c0 + ty + i) * R + r0 + tx] = __float2half_rn(t[tx][ty + i]);
}

// ---------------------------------------------------------------------------
// LayerNorm (+ residual); SPLIT writes fp16 hi/lo side-output
// ---------------------------------------------------------------------------
template <bool ADD_FIRST, bool SPLIT>
__global__ void __launch_bounds__(256)
ln_kernel(const float* __restrict__ a, const float* __restrict__ r,
          const float* __restrict__ g, const float* __restrict__ be,
          float* __restrict__ out, __half* __restrict__ oh, __half* __restrict__ ol)
{
    __shared__ float rs[8], rs2[8];
    const size_t base = (size_t)blockIdx.x * Dc;
    const int tid = threadIdx.x;
    float v[4];
    float s = 0.f, s2 = 0.f;
    #pragma unroll
    for (int j = 0; j < 4; j++) {
        const int c = tid + j * 256;
        float t = a[base + c];
        if (ADD_FIRST) t += r[base + c];
        v[j] = t; s += t; s2 += t * t;
    }
    #pragma unroll
    for (int o = 16; o; o >>= 1) {
        s  += __shfl_xor_sync(0xffffffffu, s, o);
        s2 += __shfl_xor_sync(0xffffffffu, s2, o);
    }
    if ((tid & 31) == 0) { rs[tid >> 5] = s; rs2[tid >> 5] = s2; }
    __syncthreads();
    if (tid == 0) {
        float t = 0.f, t2 = 0.f;
        for (int i = 0; i < 8; i++) { t += rs[i]; t2 += rs2[i]; }
        rs[0] = t; rs2[0] = t2;
    }
    __syncthreads();
    const float mu   = rs[0] * (1.0f / Dc);
    const float var  = rs2[0] * (1.0f / Dc) - mu * mu;
    const float rstd = rsqrtf(var + LN_EPS);
    #pragma unroll
    for (int j = 0; j < 4; j++) {
        const int c = tid + j * 256;
        float o = (v[j] - mu) * rstd * g[c] + be[c];
        if (!ADD_FIRST) o += r[base + c];
        out[base + c] = o;
        if (SPLIT) {
            const __half hb = __float2half_rn(o);
            oh[base + c] = hb;
            ol[base + c] = __float2half_rn(o - __half2float(hb));
        }
    }
}

// ---------------------------------------------------------------------------
// Launch
// ---------------------------------------------------------------------------
extern "C" void kernel_launch(void* const* d_in, const int* in_sizes, int n_in,
                              void* d_out, int out_size)
{
    (void)in_sizes; (void)n_in; (void)out_size;

    const float* q    = (const float*)d_in[0];
    const float* k    = (const float*)d_in[1];
    const float* v    = (const float*)d_in[2];
    const float* mask = (const float*)d_in[4];
    const float* Wq   = (const float*)d_in[5];
    const float* Wk   = (const float*)d_in[6];
    const float* Wv   = (const float*)d_in[7];
    const float* Wd   = (const float*)d_in[8];
    const float* W1   = (const float*)d_in[9];
    const float* b1   = (const float*)d_in[10];
    const float* W2   = (const float*)d_in[11];
    const float* b2   = (const float*)d_in[12];
    const float* g1   = (const float*)d_in[13];
    const float* be1  = (const float*)d_in[14];
    const float* g2   = (const float*)d_in[15];
    const float* be2  = (const float*)d_in[16];
    float* out = (float*)d_out;

    float *vp, *zd, *x;
    cudaGetSymbolAddress((void**)&vp, g_vp);
    cudaGetSymbolAddress((void**)&zd, g_zd);
    cudaGetSymbolAddress((void**)&x,  g_x);

    __nv_bfloat16 *qih,*qil,*kih,*kil,*vih,*vil,*wqh,*wql,*wkh,*wkl,*wvh,*wvl,*wdh,*wdl;
    __nv_bfloat16 *qph,*qpl,*kph,*kpl,*vth,*vtl,*zh,*zl,*maskb;
    __half *w1h16,*w2h16,*xh16,*xl16,*f1h16,*f1l16;
    cudaGetSymbolAddress((void**)&qih, g_qih); cudaGetSymbolAddress((void**)&qil, g_qil);
    cudaGetSymbolAddress((void**)&kih, g_kih); cudaGetSymbolAddress((void**)&kil, g_kil);
    cudaGetSymbolAddress((void**)&vih, g_vih); cudaGetSymbolAddress((void**)&vil, g_vil);
    cudaGetSymbolAddress((void**)&wqh, g_wqh); cudaGetSymbolAddress((void**)&wql, g_wql);
    cudaGetSymbolAddress((void**)&wkh, g_wkh); cudaGetSymbolAddress((void**)&wkl, g_wkl);
    cudaGetSymbolAddress((void**)&wvh, g_wvh); cudaGetSymbolAddress((void**)&wvl, g_wvl);
    cudaGetSymbolAddress((void**)&wdh, g_wdh); cudaGetSymbolAddress((void**)&wdl, g_wdl);
    cudaGetSymbolAddress((void**)&qph, g_qph); cudaGetSymbolAddress((void**)&qpl, g_qpl);
    cudaGetSymbolAddress((void**)&kph, g_kph); cudaGetSymbolAddress((void**)&kpl, g_kpl);
    cudaGetSymbolAddress((void**)&vth, g_vth); cudaGetSymbolAddress((void**)&vtl, g_vtl);
    cudaGetSymbolAddress((void**)&zh,  g_zh);  cudaGetSymbolAddress((void**)&zl,  g_zl);
    cudaGetSymbolAddress((void**)&maskb, g_maskb);
    cudaGetSymbolAddress((void**)&w1h16, g_w1h16); cudaGetSymbolAddress((void**)&w2h16, g_w2h16);
    cudaGetSymbolAddress((void**)&xh16, g_xh16);   cudaGetSymbolAddress((void**)&xl16, g_xl16);
    cudaGetSymbolAddress((void**)&f1h16, g_f1h16); cudaGetSymbolAddress((void**)&f1l16, g_f1l16);

    constexpr int SMEM128 = 2 * (32768 + 2 * 128 * 128);   // 131072 (bf16 3-term)
    constexpr int SMEM_H  = 2 * 49152;                     //  98304 (fp16 2-term)
    constexpr int SMEM_FA = 32768 + 2 * 65536;             // 163840
    cudaFuncSetAttribute(hmma_gemm<128, 0>, cudaFuncAttributeMaxDynamicSharedMemorySize, SMEM128);
    cudaFuncSetAttribute(hmma_gemm<128, 4>, cudaFuncAttributeMaxDynamicSharedMemorySize, SMEM128);
    cudaFuncSetAttribute(hmma_gemm<128, 5>, cudaFuncAttributeMaxDynamicSharedMemorySize, SMEM128);
    cudaFuncSetAttribute(hmma_gemm_h<1>, cudaFuncAttributeMaxDynamicSharedMemorySize, SMEM_H);
    cudaFuncSetAttribute(hmma_gemm_h<2>, cudaFuncAttributeMaxDynamicSharedMemorySize, SMEM_H);
    cudaFuncSetAttribute(fa_kernel, cudaFuncAttributeMaxDynamicSharedMemorySize, SMEM_FA);

    const dim3 b256(256);

    // ---- weight transpose + split ----
    tsplit_kernel<<<dim3(32, 32, 1),  b256>>>(Wq, wqh, wql, Dc, Dc, 0, 0);
    tsplit_kernel<<<dim3(32, 32, 1),  b256>>>(Wk, wkh, wkl, Dc, Dc, 0, 0);
    tsplit_kernel<<<dim3(32, 32, 1),  b256>>>(Wv, wvh, wvl, Dc, Dc, 0, 0);
    tsplit_kernel<<<dim3(32, 32, 1),  b256>>>(Wd, wdh, wdl, Dc, Dc, 0, 0);
    tsplit_h_kernel<<<dim3(128, 32, 1), b256>>>(W1, w1h16, Dc, FFc);
    tsplit_h_kernel<<<dim3(32, 128, 1), b256>>>(W2, w2h16, FFc, Dc);

    // ---- mask -> bf16 ----
    maskbf_kernel<<<(unsigned)((long long)Sc * Sc / 1024), b256>>>(
        mask, maskb, (long long)Sc * Sc);

    // ---- input splits ----
    const long long nBD = (long long)BS * Dc;
    split_kernel<<<(unsigned)(nBD / 1024), b256>>>(q, qih, qil, nBD);
    split_kernel<<<(unsigned)(nBD / 1024), b256>>>(k, kih, kil, nBD);
    split_kernel<<<(unsigned)(nBD / 1024), b256>>>(v, vih, vil, nBD);

    // ---- QKV projections (Q gets 0.125 pre-scale) ----
    hmma_gemm<128, 5><<<dim3(8, 32, 1), b256, SMEM128>>>(
        qih, qil, Dc, wqh, wql, Dc, nullptr, qph, qpl, Dc, Dc, nullptr);
    hmma_gemm<128, 4><<<dim3(8, 32, 1), b256, SMEM128>>>(
        kih, kil, Dc, wkh, wkl, Dc, nullptr, kph, kpl, Dc, Dc, nullptr);
    hmma_gemm<128, 0><<<dim3(8, 32, 1), b256, SMEM128>>>(
        vih, vil, Dc, wvh, wvl, Dc, vp, nullptr, nullptr, Dc, Dc, nullptr);

    // ---- transpose V per batch to [D, S] hi/lo ----
    tsplit_kernel<<<dim3(32, 64, 2), b256>>>(vp, vth, vtl, Sc, Dc,
                                             (long long)Sc * Dc, (long long)Dc * Sc);

    // ---- fused flash attention -> zh/zl ----
    fa_kernel<<<dim3(Sc / 128, Bc * Hc), b256, SMEM_FA>>>(
        qph, qpl, kph, kpl, vth, vtl, maskb, zh, zl);

    // ---- zd = z @ Wd ----
    hmma_gemm<128, 0><<<dim3(8, 32, 1), b256, SMEM128>>>(
        zh, zl, Dc, wdh, wdl, Dc, zd, nullptr, nullptr, Dc, Dc, nullptr);

    // ---- x = LN(zd)*g1 + be1 + q  (+ fp16 split) ----
    ln_kernel<false, true><<<BS, b256>>>(zd, q, g1, be1, x, xh16, xl16);

    // ---- FFN (fp16 2-term) ----
    hmma_gemm_h<2><<<dim3(32, 32, 1), b256, SMEM_H>>>(
        xh16, xl16, Dc, w1h16, Dc, nullptr, f1h16, f1l16, FFc, Dc, b1);
    hmma_gemm_h<1><<<dim3(8, 32, 1), b256, SMEM_H>>>(
        f1h16, f1l16, FFc, w2h16, FFc, zd, nullptr, nullptr, Dc, FFc, b2);

    // ---- out = LN(ff2 + x)*g2 + be2 ----
    ln_kernel<true, false><<<BS, b256>>>(zd, x, g2, be2, out, nullptr, nullptr);
}

// round 15
// speedup vs baseline: 1.2046x; 1.2046x over previous
#include <cuda_runtime.h>
#include <cuda_bf16.h>
#include <cuda_fp16.h>
#include <cstdint>

// ---------------------------------------------------------------------------
// Problem constants
// ---------------------------------------------------------------------------
constexpr int Bc  = 2;
constexpr int Sc  = 2048;
constexpr int Dc  = 1024;
constexpr int Hc  = 16;
constexpr int DHc = 64;
constexpr int FFc = 4096;
constexpr int BS  = Bc * Sc;
constexpr float LN_EPS = 1e-5f;

// ---------------------------------------------------------------------------
// Scratch (device globals; allocation is forbidden)
// ---------------------------------------------------------------------------
__device__ float g_zd[BS * Dc];
__device__ float g_x [BS * Dc];

__device__ __nv_bfloat16 g_maskb[(size_t)Sc*Sc];                 // bf16 mask (range-safe)

// fp16 path
__device__ __half g_qih16[BS*Dc], g_qil16[BS*Dc];
__device__ __half g_kih16[BS*Dc], g_kil16[BS*Dc];
__device__ __half g_vih16[BS*Dc], g_vil16[BS*Dc];
__device__ __half g_wq16[Dc*Dc], g_wk16[Dc*Dc], g_wv16[Dc*Dc], g_wd16[Dc*Dc];
__device__ __half g_w1h16[(size_t)FFc*Dc];                       // [4096,1024] K-major
__device__ __half g_w2h16[(size_t)Dc*FFc];                       // [1024,4096] K-major
__device__ __half g_qph16[BS*Dc], g_qpl16[BS*Dc];                // Q proj (pre-scaled 0.125)
__device__ __half g_kp16[BS*Dc];                                 // K proj (single)
__device__ __half g_vt16[BS*Dc];                                 // V proj transposed [B, D, S]
__device__ __half g_zh16[BS*Dc], g_zl16[BS*Dc];
__device__ __half g_xh16[BS*Dc], g_xl16[BS*Dc];
__device__ __half g_f1h16[(size_t)BS*FFc], g_f1l16[(size_t)BS*FFc];

// ---------------------------------------------------------------------------
// PTX helpers (legal on plain compute_103)
// ---------------------------------------------------------------------------
__device__ __forceinline__ uint32_t s2u(const void* p) {
    uint32_t a;
    asm("{ .reg .u64 t; cvta.to.shared.u64 t, %1; cvt.u32.u64 %0, t; }" : "=r"(a) : "l"(p));
    return a;
}
#define SWZ(x) ((x) ^ (((x) >> 3) & 0x70))
#define CPA16(dst, src) asm volatile("cp.async.cg.shared.global [%0], [%1], 16;" :: "r"(dst), "l"(src))
#define CPA_COMMIT()    asm volatile("cp.async.commit_group;" ::: "memory")
#define CPA_WAIT(n)     asm volatile("cp.async.wait_group %0;" :: "n"(n) : "memory")

__device__ __forceinline__ void ldsm4(uint32_t* r, uint32_t addr) {
    asm volatile("ldmatrix.sync.aligned.m8n8.x4.shared.b16 {%0,%1,%2,%3}, [%4];"
        : "=r"(r[0]), "=r"(r[1]), "=r"(r[2]), "=r"(r[3]) : "r"(addr));
}
__device__ __forceinline__ void mma16816h(float* c, const uint32_t* a, const uint32_t* b) {
    asm volatile("mma.sync.aligned.m16n8k16.row.col.f32.f16.f16.f32 "
        "{%0,%1,%2,%3}, {%4,%5,%6,%7}, {%8,%9}, {%0,%1,%2,%3};"
        : "+f"(c[0]), "+f"(c[1]), "+f"(c[2]), "+f"(c[3])
        : "r"(a[0]), "r"(a[1]), "r"(a[2]), "r"(a[3]), "r"(b[0]), "r"(b[1]));
}
__device__ __forceinline__ uint32_t packbf2(float lo, float hi) {
    uint32_t r;
    asm("cvt.rn.bf16x2.f32 %0, %1, %2;" : "=r"(r) : "f"(hi), "f"(lo));
    return r;
}
__device__ __forceinline__ uint32_t packh2(float lo, float hi) {
    uint32_t r;
    asm("cvt.rn.f16x2.f32 %0, %1, %2;" : "=r"(r) : "f"(hi), "f"(lo));
    return r;
}
__device__ __forceinline__ float h_round(float x) {
    return __half2float(__float2half_rn(x));
}

// ---------------------------------------------------------------------------
// fp16 HMMA GEMM (2-term): C[M,N] = (Ah+Al)[M,K] @ B^T, B [N,K] K-major fp16.
// 128x128 tile. Stage 48K; 2 stages = 96K -> 2 CTAs/SM.
// EPI: 0 fp32, 1 bias+fp32, 2 bias+relu+fp16split, 4 fp16split,
//      5 scale0.125+fp16split, 6 fp16 single, 7 fp16 single transposed [B,D,S]
// ---------------------------------------------------------------------------
template <int EPI>
__global__ void __launch_bounds__(256, 2)
hmma_gemm_h(const __half* __restrict__ Ah_, const __half* __restrict__ Al_, int lda,
            const __half* __restrict__ B_, int ldb,
            float* __restrict__ C_, __half* __restrict__ Ch_, __half* __restrict__ Cl_,
            int ldc, int K, const float* __restrict__ bias)
{
    constexpr int AOFF  = 16384;
    constexpr int BOFF  = 32768;
    constexpr int STAGE = 49152;

    extern __shared__ __align__(1024) char smem[];
    const uint32_t sbase = s2u(smem);

    const int tid  = threadIdx.x;
    const int wid  = tid >> 5;
    const int lane = tid & 31;
    const int warp_m = wid & 1;
    const int warp_n = wid >> 1;

    const int m0 = blockIdx.y * 128;
    const int n0 = blockIdx.x * 128;
    const int NC = K >> 6;

    float acc[4][4][4];
    #pragma unroll
    for (int i = 0; i < 4; i++)
        #pragma unroll
        for (int j = 0; j < 4; j++)
            #pragma unroll
            for (int e = 0; e < 4; e++) acc[i][j][e] = 0.f;

    auto load_chunk = [&](int c, int s) {
        const uint32_t s0 = sbase + s * STAGE;
        const int kk = c * 64;
        #pragma unroll
        for (int i = 0; i < 4; i++) {
            const int e = tid + i * 256;
            const int row = e >> 3, c16 = e & 7;
            const uint32_t off = SWZ(row * 128 + c16 * 16);
            const size_t go = (size_t)(m0 + row) * lda + kk + c16 * 8;
            CPA16(s0 + off,        Ah_ + go);
            CPA16(s0 + AOFF + off, Al_ + go);
        }
        #pragma unroll
        for (int i = 0; i < 4; i++) {
            const int e = tid + i * 256;
            const int row = e >> 3, c16 = e & 7;
            const uint32_t off = SWZ(row * 128 + c16 * 16);
            CPA16(s0 + BOFF + off, B_ + (size_t)(n0 + row) * ldb + kk + c16 * 8);
        }
    };

    load_chunk(0, 0); CPA_COMMIT();
    if (NC > 1) { load_chunk(1, 1); CPA_COMMIT(); }

    const int a_r = lane & 15;
    const int a_k = (lane >> 4) & 1;
    const int b_r = lane & 7;
    const int b_k = (lane >> 3) & 1;
    const int b_n = (lane >> 4) & 1;

    for (int c = 0; c < NC; c++) {
        if (c + 1 < NC) { CPA_WAIT(1); } else { CPA_WAIT(0); }
        __syncthreads();
        const uint32_t s0 = sbase + (c & 1) * STAGE;

        #pragma unroll
        for (int ks = 0; ks < 4; ks++) {
            uint32_t bh[8];
            #pragma unroll
            for (int j2 = 0; j2 < 2; j2++) {
                const uint32_t off = SWZ((warp_n * 32 + j2 * 16 + b_n * 8 + b_r) * 128 + ks * 32 + b_k * 16);
                ldsm4(&bh[j2 * 4], s0 + BOFF + off);
            }
            #pragma unroll
            for (int im = 0; im < 4; im++) {
                uint32_t ah[4], al[4];
                const uint32_t off = SWZ((warp_m * 64 + im * 16 + a_r) * 128 + ks * 32 + a_k * 16);
                ldsm4(ah, s0 + off);
                ldsm4(al, s0 + AOFF + off);
                #pragma unroll
                for (int jn = 0; jn < 4; jn++) {
                    mma16816h(acc[im][jn], ah, &bh[jn * 2]);
                    mma16816h(acc[im][jn], al, &bh[jn * 2]);
                }
            }
        }
        __syncthreads();
        if (c + 2 < NC) { load_chunk(c + 2, c & 1); CPA_COMMIT(); }
    }

    const int qr = lane >> 2;
    const int qc = (lane & 3) * 2;
    #pragma unroll
    for (int im = 0; im < 4; im++) {
        const int m = m0 + warp_m * 64 + im * 16 + qr;
        #pragma unroll
        for (int jn = 0; jn < 4; jn++) {
            const int n = n0 + warp_n * 32 + jn * 8 + qc;
            float2 v0 = make_float2(acc[im][jn][0], acc[im][jn][1]);
            float2 v1 = make_float2(acc[im][jn][2], acc[im][jn][3]);
            if (EPI == 1 || EPI == 2) {
                const float2 bv = *reinterpret_cast<const float2*>(bias + n);
                v0.x += bv.x; v0.y += bv.y; v1.x += bv.x; v1.y += bv.y;
            }
            if (EPI == 5) {
                v0.x *= 0.125f; v0.y *= 0.125f; v1.x *= 0.125f; v1.y *= 0.125f;
            }
            if (EPI == 2) {
                v0.x = fmaxf(v0.x, 0.f); v0.y = fmaxf(v0.y, 0.f);
                v1.x = fmaxf(v1.x, 0.f); v1.y = fmaxf(v1.y, 0.f);
            }
            if (EPI == 2 || EPI == 4 || EPI == 5) {
                *reinterpret_cast<uint32_t*>(Ch_ + (size_t)m * ldc + n)       = packh2(v0.x, v0.y);
                *reinterpret_cast<uint32_t*>(Ch_ + (size_t)(m + 8) * ldc + n) = packh2(v1.x, v1.y);
                *reinterpret_cast<uint32_t*>(Cl_ + (size_t)m * ldc + n)       =
                    packh2(v0.x - h_round(v0.x), v0.y - h_round(v0.y));
                *reinterpret_cast<uint32_t*>(Cl_ + (size_t)(m + 8) * ldc + n) =
                    packh2(v1.x - h_round(v1.x), v1.y - h_round(v1.y));
            } else if (EPI == 6) {
                *reinterpret_cast<uint32_t*>(Ch_ + (size_t)m * ldc + n)       = packh2(v0.x, v0.y);
                *reinterpret_cast<uint32_t*>(Ch_ + (size_t)(m + 8) * ldc + n) = packh2(v1.x, v1.y);
            } else if (EPI == 7) {
                // transposed per-batch: out[b, n, s] ; batch = m>>11, s = m&2047
                const size_t base = (size_t)(m >> 11) * Dc * Sc;
                const int s_ = m & 2047;
                Ch_[base + (size_t)n * Sc + s_]           = __float2half_rn(v0.x);
                Ch_[base + (size_t)(n + 1) * Sc + s_]     = __float2half_rn(v0.y);
                Ch_[base + (size_t)n * Sc + s_ + 8]       = __float2half_rn(v1.x);
                Ch_[base + (size_t)(n + 1) * Sc + s_ + 8] = __float2half_rn(v1.y);
            } else {
                *reinterpret_cast<float2*>(C_ + (size_t)m * ldc + n)       = v0;
                *reinterpret_cast<float2*>(C_ + (size_t)(m + 8) * ldc + n) = v1;
            }
        }
    }
}

// ---------------------------------------------------------------------------
// Fused FlashAttention, fp16 2-term (Q pre-scaled 0.125; K,V single fp16)
// Q [S,D] hi/lo, K [S,D], V^T [B,D,S]; z out fp16 hi/lo [S,D] merged heads.
// smem: Q 32K + 2 stages x (K 16K + V 16K) = 96K.
// ---------------------------------------------------------------------------
__global__ void __launch_bounds__(256)
fa_kernel(const __half* __restrict__ qh_, const __half* __restrict__ ql_,
          const __half* __restrict__ k_,
          const __half* __restrict__ vt_,
          const __nv_bfloat16* __restrict__ maskb,
          __half* __restrict__ zh, __half* __restrict__ zl)
{
    constexpr int QH = 0, QL = 16384;
    constexpr int ST0 = 32768, STB = 32768;
    constexpr int KHo = 0, VHo = 16384;
    constexpr int NT = Sc / 128;

    extern __shared__ __align__(1024) char smem[];
    const uint32_t sbase = s2u(smem);

    const int tid  = threadIdx.x;
    const int wid  = tid >> 5;
    const int lane = tid & 31;

    const int z = blockIdx.y;
    const int b = z >> 4, h = z & 15;
    const int m0 = blockIdx.x * 128;

    const __half* Qh = qh_ + ((size_t)(b * Sc + m0)) * Dc + h * DHc;
    const __half* Ql = ql_ + ((size_t)(b * Sc + m0)) * Dc + h * DHc;
    const __half* Kp = k_  + (size_t)b * Sc * Dc + h * DHc;
    const __half* Vp = vt_ + ((size_t)b * Dc + h * DHc) * Sc;

    #pragma unroll
    for (int i = 0; i < 4; i++) {
        const int e = tid + i * 256;
        const int row = e >> 3, c16 = e & 7;
        const uint32_t off = SWZ(row * 128 + c16 * 16);
        const size_t go = (size_t)row * Dc + c16 * 8;
        CPA16(sbase + QH + off, Qh + go);
        CPA16(sbase + QL + off, Ql + go);
    }
    auto load_kv = [&](int kt, int s) {
        const uint32_t s0 = sbase + ST0 + s * STB;
        #pragma unroll
        for (int i = 0; i < 4; i++) {
            const int e = tid + i * 256;
            const int row = e >> 3, c16 = e & 7;
            const uint32_t off = SWZ(row * 128 + c16 * 16);
            CPA16(s0 + KHo + off, Kp + (size_t)(kt * 128 + row) * Dc + c16 * 8);
        }
        #pragma unroll
        for (int i = 0; i < 4; i++) {
            const int e = tid + i * 256;
            const int row = e >> 4, c16 = e & 15;
            const uint32_t off = SWZ(row * 256 + c16 * 16);
            CPA16(s0 + VHo + off, Vp + (size_t)row * Sc + kt * 128 + c16 * 8);
        }
    };
    load_kv(0, 0); CPA_COMMIT();
    load_kv(1, 1); CPA_COMMIT();

    const int a_r = lane & 15;
    const int a_k = (lane >> 4) & 1;
    const int b_r = lane & 7;
    const int b_k = (lane >> 3) & 1;
    const int b_n = (lane >> 4) & 1;
    const int qr  = lane >> 2;
    const int qc  = (lane & 3) * 2;

    float O[8][4];
    #pragma unroll
    for (int j = 0; j < 8; j++)
        #pragma unroll
        for (int e = 0; e < 4; e++) O[j][e] = 0.f;
    float pm0 = -1e30f, pm1 = -1e30f, l0 = 0.f, l1 = 0.f;

    const int row0 = m0 + wid * 16 + qr;
    const __nv_bfloat16* mrow0 = maskb + (size_t)row0 * Sc;
    const __nv_bfloat16* mrow1 = maskb + (size_t)(row0 + 8) * Sc;

    for (int kt = 0; kt < NT; kt++) {
        if (kt + 1 < NT) { CPA_WAIT(1); } else { CPA_WAIT(0); }
        __syncthreads();
        const uint32_t s0 = sbase + ST0 + (kt & 1) * STB;

        float s[16][4];
        #pragma unroll
        for (int j = 0; j < 16; j++)
            #pragma unroll
            for (int e = 0; e < 4; e++) s[j][e] = 0.f;

        #pragma unroll
        for (int ks = 0; ks < 4; ks++) {
            uint32_t ah[4], al[4];
            {
                const uint32_t off = SWZ((wid * 16 + a_r) * 128 + ks * 32 + a_k * 16);
                ldsm4(ah, sbase + QH + off);
                ldsm4(al, sbase + QL + off);
            }
            #pragma unroll
            for (int j2 = 0; j2 < 8; j2++) {
                uint32_t bh[4];
                const uint32_t off = SWZ((j2 * 16 + b_n * 8 + b_r) * 128 + ks * 32 + b_k * 16);
                ldsm4(bh, s0 + KHo + off);
                mma16816h(s[j2 * 2],     ah, bh);
                mma16816h(s[j2 * 2],     al, bh);
                mma16816h(s[j2 * 2 + 1], ah, bh + 2);
                mma16816h(s[j2 * 2 + 1], al, bh + 2);
            }
        }

        float mx0 = -1e30f, mx1 = -1e30f;
        #pragma unroll
        for (int jn = 0; jn < 16; jn++) {
            const int col = kt * 128 + jn * 8 + qc;
            const float2 mv0 = __bfloat1622float2(
                *reinterpret_cast<const __nv_bfloat162*>(mrow0 + col));
            const float2 mv1 = __bfloat1622float2(
                *reinterpret_cast<const __nv_bfloat162*>(mrow1 + col));
            s[jn][0] += mv0.x;
            s[jn][1] += mv0.y;
            s[jn][2] += mv1.x;
            s[jn][3] += mv1.y;
            mx0 = fmaxf(mx0, fmaxf(s[jn][0], s[jn][1]));
            mx1 = fmaxf(mx1, fmaxf(s[jn][2], s[jn][3]));
        }
        mx0 = fmaxf(mx0, __shfl_xor_sync(0xffffffffu, mx0, 1));
        mx0 = fmaxf(mx0, __shfl_xor_sync(0xffffffffu, mx0, 2));
        mx1 = fmaxf(mx1, __shfl_xor_sync(0xffffffffu, mx1, 1));
        mx1 = fmaxf(mx1, __shfl_xor_sync(0xffffffffu, mx1, 2));
        const float nm0 = fmaxf(pm0, mx0), nm1 = fmaxf(pm1, mx1);
        const float sc0 = __expf(pm0 - nm0), sc1 = __expf(pm1 - nm1);
        l0 *= sc0; l1 *= sc1;
        #pragma unroll
        for (int j = 0; j < 8; j++) {
            O[j][0] *= sc0; O[j][1] *= sc0; O[j][2] *= sc1; O[j][3] *= sc1;
        }
        float sum0 = 0.f, sum1 = 0.f;
        #pragma unroll
        for (int jn = 0; jn < 16; jn++) {
            s[jn][0] = __expf(s[jn][0] - nm0);
            s[jn][1] = __expf(s[jn][1] - nm0);
            s[jn][2] = __expf(s[jn][2] - nm1);
            s[jn][3] = __expf(s[jn][3] - nm1);
            sum0 += s[jn][0] + s[jn][1];
            sum1 += s[jn][2] + s[jn][3];
        }
        sum0 += __shfl_xor_sync(0xffffffffu, sum0, 1);
        sum0 += __shfl_xor_sync(0xffffffffu, sum0, 2);
        sum1 += __shfl_xor_sync(0xffffffffu, sum1, 1);
        sum1 += __shfl_xor_sync(0xffffffffu, sum1, 2);
        l0 += sum0; l1 += sum1;
        pm0 = nm0; pm1 = nm1;

        #pragma unroll
        for (int ks2 = 0; ks2 < 8; ks2++) {
            uint32_t ph[4], pl[4];
            {
                const float p00 = s[2 * ks2][0],     p01 = s[2 * ks2][1];
                const float p10 = s[2 * ks2][2],     p11 = s[2 * ks2][3];
                const float p20 = s[2 * ks2 + 1][0], p21 = s[2 * ks2 + 1][1];
                const float p30 = s[2 * ks2 + 1][2], p31 = s[2 * ks2 + 1][3];
                ph[0] = packh2(p00, p01);
                ph[1] = packh2(p10, p11);
                ph[2] = packh2(p20, p21);
                ph[3] = packh2(p30, p31);
                pl[0] = packh2(p00 - h_round(p00), p01 - h_round(p01));
                pl[1] = packh2(p10 - h_round(p10), p11 - h_round(p11));
                pl[2] = packh2(p20 - h_round(p20), p21 - h_round(p21));
                pl[3] = packh2(p30 - h_round(p30), p31 - h_round(p31));
            }
            #pragma unroll
            for (int j2 = 0; j2 < 4; j2++) {
                uint32_t vh2[4];
                const uint32_t off = SWZ((j2 * 16 + b_n * 8 + b_r) * 256 + ks2 * 32 + b_k * 16);
                ldsm4(vh2, s0 + VHo + off);
                mma16816h(O[j2 * 2],     ph, vh2);
                mma16816h(O[j2 * 2],     pl, vh2);
                mma16816h(O[j2 * 2 + 1], ph, vh2 + 2);
                mma16816h(O[j2 * 2 + 1], pl, vh2 + 2);
            }
        }

        __syncthreads();
        if (kt + 2 < NT) { load_kv(kt + 2, kt & 1); CPA_COMMIT(); }
    }

    const float inv0 = 1.0f / l0, inv1 = 1.0f / l1;
    const size_t r0 = (size_t)(b * Sc + row0) * Dc + h * DHc;
    const size_t r1 = r0 + 8 * Dc;
    #pragma unroll
    for (int jn = 0; jn < 8; jn++) {
        const int n = jn * 8 + qc;
        const float a = O[jn][0] * inv0, bb = O[jn][1] * inv0;
        const float c = O[jn][2] * inv1, d  = O[jn][3] * inv1;
        *reinterpret_cast<uint32_t*>(zh + r0 + n) = packh2(a, bb);
        *reinterpret_cast<uint32_t*>(zl + r0 + n) = packh2(a - h_round(a), bb - h_round(bb));
        *reinterpret_cast<uint32_t*>(zh + r1 + n) = packh2(c, d);
        *reinterpret_cast<uint32_t*>(zl + r1 + n) = packh2(c - h_round(c), d - h_round(d));
    }
}

// ---------------------------------------------------------------------------
// Elementwise helpers
// ---------------------------------------------------------------------------
__global__ void __launch_bounds__(256)
split_h_kernel(const float* __restrict__ x, __half* __restrict__ h,
               __half* __restrict__ l, long long n)
{
    const long long i = ((long long)blockIdx.x * 256 + threadIdx.x) * 4;
    if (i >= n) return;
    const float4 v = *reinterpret_cast<const float4*>(x + i);
    uint32_t* hp = reinterpret_cast<uint32_t*>(h + i);
    uint32_t* lp = reinterpret_cast<uint32_t*>(l + i);
    hp[0] = packh2(v.x, v.y); hp[1] = packh2(v.z, v.w);
    lp[0] = packh2(v.x - h_round(v.x), v.y - h_round(v.y));
    lp[1] = packh2(v.z - h_round(v.z), v.w - h_round(v.w));
}

__global__ void __launch_bounds__(256)
maskbf_kernel(const float* __restrict__ m, __nv_bfloat16* __restrict__ o, long long n)
{
    const long long i = ((long long)blockIdx.x * 256 + threadIdx.x) * 4;
    if (i >= n) return;
    const float4 v = *reinterpret_cast<const float4*>(m + i);
    uint32_t* op = reinterpret_cast<uint32_t*>(o + i);
    op[0] = packbf2(v.x, v.y); op[1] = packbf2(v.z, v.w);
}

// transpose fp32 [R, C] -> fp16 [C, R] (weights, single precision)
__global__ void __launch_bounds__(256)
tsplit_h_kernel(const float* __restrict__ in, __half* __restrict__ oh, int R, int Ccols)
{
    __shared__ float t[32][33];
    const int c0 = blockIdx.x * 32, r0 = blockIdx.y * 32;
    const int tx = threadIdx.x & 31, ty = threadIdx.x >> 5;
    #pragma unroll
    for (int i = 0; i < 32; i += 8)
        t[ty + i][tx] = in[(size_t)(r0 + ty + i) * Ccols + c0 + tx];
    __syncthreads();
    #pragma unroll
    for (int i = 0; i < 32; i += 8)
        oh[(size_t)(c0 + ty + i) * R + r0 + tx] = __float2half_rn(t[tx][ty + i]);
}

// ---------------------------------------------------------------------------
// LayerNorm (+ residual); SPLIT writes fp16 hi/lo side-output
// ---------------------------------------------------------------------------
template <bool ADD_FIRST, bool SPLIT>
__global__ void __launch_bounds__(256)
ln_kernel(const float* __restrict__ a, const float* __restrict__ r,
          const float* __restrict__ g, const float* __restrict__ be,
          float* __restrict__ out, __half* __restrict__ oh, __half* __restrict__ ol)
{
    __shared__ float rs[8], rs2[8];
    const size_t base = (size_t)blockIdx.x * Dc;
    const int tid = threadIdx.x;
    float v[4];
    float s = 0.f, s2 = 0.f;
    #pragma unroll
    for (int j = 0; j < 4; j++) {
        const int c = tid + j * 256;
        float t = a[base + c];
        if (ADD_FIRST) t += r[base + c];
        v[j] = t; s += t; s2 += t * t;
    }
    #pragma unroll
    for (int o = 16; o; o >>= 1) {
        s  += __shfl_xor_sync(0xffffffffu, s, o);
        s2 += __shfl_xor_sync(0xffffffffu, s2, o);
    }
    if ((tid & 31) == 0) { rs[tid >> 5] = s; rs2[tid >> 5] = s2; }
    __syncthreads();
    if (tid == 0) {
        float t = 0.f, t2 = 0.f;
        for (int i = 0; i < 8; i++) { t += rs[i]; t2 += rs2[i]; }
        rs[0] = t; rs2[0] = t2;
    }
    __syncthreads();
    const float mu   = rs[0] * (1.0f / Dc);
    const float var  = rs2[0] * (1.0f / Dc) - mu * mu;
    const float rstd = rsqrtf(var + LN_EPS);
    #pragma unroll
    for (int j = 0; j < 4; j++) {
        const int c = tid + j * 256;
        float o = (v[j] - mu) * rstd * g[c] + be[c];
        if (!ADD_FIRST) o += r[base + c];
        out[base + c] = o;
        if (SPLIT) {
            const __half hb = __float2half_rn(o);
            oh[base + c] = hb;
            ol[base + c] = __float2half_rn(o - __half2float(hb));
        }
    }
}

// ---------------------------------------------------------------------------
// Launch
// ---------------------------------------------------------------------------
extern "C" void kernel_launch(void* const* d_in, const int* in_sizes, int n_in,
                              void* d_out, int out_size)
{
    (void)in_sizes; (void)n_in; (void)out_size;

    const float* q    = (const float*)d_in[0];
    const float* k    = (const float*)d_in[1];
    const float* v    = (const float*)d_in[2];
    const float* mask = (const float*)d_in[4];
    const float* Wq   = (const float*)d_in[5];
    const float* Wk   = (const float*)d_in[6];
    const float* Wv   = (const float*)d_in[7];
    const float* Wd   = (const float*)d_in[8];
    const float* W1   = (const float*)d_in[9];
    const float* b1   = (const float*)d_in[10];
    const float* W2   = (const float*)d_in[11];
    const float* b2   = (const float*)d_in[12];
    const float* g1   = (const float*)d_in[13];
    const float* be1  = (const float*)d_in[14];
    const float* g2   = (const float*)d_in[15];
    const float* be2  = (const float*)d_in[16];
    float* out = (float*)d_out;

    float *zd, *x;
    cudaGetSymbolAddress((void**)&zd, g_zd);
    cudaGetSymbolAddress((void**)&x,  g_x);

    __nv_bfloat16 *maskb;
    __half *qih,*qil,*kih,*kil,*vih,*vil,*wq16,*wk16,*wv16,*wd16,*w1h16,*w2h16;
    __half *qph,*qpl,*kp16,*vt16,*zh16,*zl16,*xh16,*xl16,*f1h16,*f1l16;
    cudaGetSymbolAddress((void**)&maskb, g_maskb);
    cudaGetSymbolAddress((void**)&qih, g_qih16); cudaGetSymbolAddress((void**)&qil, g_qil16);
    cudaGetSymbolAddress((void**)&kih, g_kih16); cudaGetSymbolAddress((void**)&kil, g_kil16);
    cudaGetSymbolAddress((void**)&vih, g_vih16); cudaGetSymbolAddress((void**)&vil, g_vil16);
    cudaGetSymbolAddress((void**)&wq16, g_wq16); cudaGetSymbolAddress((void**)&wk16, g_wk16);
    cudaGetSymbolAddress((void**)&wv16, g_wv16); cudaGetSymbolAddress((void**)&wd16, g_wd16);
    cudaGetSymbolAddress((void**)&w1h16, g_w1h16); cudaGetSymbolAddress((void**)&w2h16, g_w2h16);
    cudaGetSymbolAddress((void**)&qph, g_qph16); cudaGetSymbolAddress((void**)&qpl, g_qpl16);
    cudaGetSymbolAddress((void**)&kp16, g_kp16); cudaGetSymbolAddress((void**)&vt16, g_vt16);
    cudaGetSymbolAddress((void**)&zh16, g_zh16); cudaGetSymbolAddress((void**)&zl16, g_zl16);
    cudaGetSymbolAddress((void**)&xh16, g_xh16); cudaGetSymbolAddress((void**)&xl16, g_xl16);
    cudaGetSymbolAddress((void**)&f1h16, g_f1h16); cudaGetSymbolAddress((void**)&f1l16, g_f1l16);

    constexpr int SMEM_H  = 2 * 49152;          //  98304 (fp16 2-term GEMM)
    constexpr int SMEM_FA = 32768 + 2 * 32768;  //  98304 (FA fp16)
    cudaFuncSetAttribute(hmma_gemm_h<0>, cudaFuncAttributeMaxDynamicSharedMemorySize, SMEM_H);
    cudaFuncSetAttribute(hmma_gemm_h<1>, cudaFuncAttributeMaxDynamicSharedMemorySize, SMEM_H);
    cudaFuncSetAttribute(hmma_gemm_h<2>, cudaFuncAttributeMaxDynamicSharedMemorySize, SMEM_H);
    cudaFuncSetAttribute(hmma_gemm_h<5>, cudaFuncAttributeMaxDynamicSharedMemorySize, SMEM_H);
    cudaFuncSetAttribute(hmma_gemm_h<6>, cudaFuncAttributeMaxDynamicSharedMemorySize, SMEM_H);
    cudaFuncSetAttribute(hmma_gemm_h<7>, cudaFuncAttributeMaxDynamicSharedMemorySize, SMEM_H);
    cudaFuncSetAttribute(fa_kernel, cudaFuncAttributeMaxDynamicSharedMemorySize, SMEM_FA);

    const dim3 b256(256);

    // ---- weight transpose (fp16 single) ----
    tsplit_h_kernel<<<dim3(32, 32, 1),  b256>>>(Wq, wq16, Dc, Dc);
    tsplit_h_kernel<<<dim3(32, 32, 1),  b256>>>(Wk, wk16, Dc, Dc);
    tsplit_h_kernel<<<dim3(32, 32, 1),  b256>>>(Wv, wv16, Dc, Dc);
    tsplit_h_kernel<<<dim3(32, 32, 1),  b256>>>(Wd, wd16, Dc, Dc);
    tsplit_h_kernel<<<dim3(128, 32, 1), b256>>>(W1, w1h16, Dc, FFc);
    tsplit_h_kernel<<<dim3(32, 128, 1), b256>>>(W2, w2h16, FFc, Dc);

    // ---- mask -> bf16 ----
    maskbf_kernel<<<(unsigned)((long long)Sc * Sc / 1024), b256>>>(
        mask, maskb, (long long)Sc * Sc);

    // ---- input splits (fp16 2-term) ----
    const long long nBD = (long long)BS * Dc;
    split_h_kernel<<<(unsigned)(nBD / 1024), b256>>>(q, qih, qil, nBD);
    split_h_kernel<<<(unsigned)(nBD / 1024), b256>>>(k, kih, kil, nBD);
    split_h_kernel<<<(unsigned)(nBD / 1024), b256>>>(v, vih, vil, nBD);

    // ---- QKV projections ----
    hmma_gemm_h<5><<<dim3(8, 32, 1), b256, SMEM_H>>>(        // Q: x0.125 + 2-term
        qih, qil, Dc, wq16, Dc, nullptr, qph, qpl, Dc, Dc, nullptr);
    hmma_gemm_h<6><<<dim3(8, 32, 1), b256, SMEM_H>>>(        // K: single fp16
        kih, kil, Dc, wk16, Dc, nullptr, kp16, nullptr, Dc, Dc, nullptr);
    hmma_gemm_h<7><<<dim3(8, 32, 1), b256, SMEM_H>>>(        // V: single fp16, transposed
        vih, vil, Dc, wv16, Dc, nullptr, vt16, nullptr, 0, Dc, nullptr);

    // ---- fused flash attention -> zh/zl ----
    fa_kernel<<<dim3(Sc / 128, Bc * Hc), b256, SMEM_FA>>>(
        qph, qpl, kp16, vt16, maskb, zh16, zl16);

    // ---- zd = z @ Wd ----
    hmma_gemm_h<0><<<dim3(8, 32, 1), b256, SMEM_H>>>(
        zh16, zl16, Dc, wd16, Dc, zd, nullptr, nullptr, Dc, Dc, nullptr);

    // ---- x = LN(zd)*g1 + be1 + q  (+ fp16 split) ----
    ln_kernel<false, true><<<BS, b256>>>(zd, q, g1, be1, x, xh16, xl16);

    // ---- FFN (fp16 2-term) ----
    hmma_gemm_h<2><<<dim3(32, 32, 1), b256, SMEM_H>>>(
        xh16, xl16, Dc, w1h16, Dc, nullptr, f1h16, f1l16, FFc, Dc, b1);
    hmma_gemm_h<1><<<dim3(8, 32, 1), b256, SMEM_H>>>(
        f1h16, f1l16, FFc, w2h16, FFc, zd, nullptr, nullptr, Dc, FFc, b2);

    // ---- out = LN(ff2 + x)*g2 + be2 ----
    ln_kernel<true, false><<<BS, b256>>>(zd, x, g2, be2, out, nullptr, nullptr);
}

// round 16
// speedup vs baseline: 1.3980x; 1.1606x over previous
#include <cuda_runtime.h>
#include <cuda_bf16.h>
#include <cuda_fp16.h>
#include <cstdint>

// ---------------------------------------------------------------------------
// Problem constants
// ---------------------------------------------------------------------------
constexpr int Bc  = 2;
constexpr int Sc  = 2048;
constexpr int Dc  = 1024;
constexpr int Hc  = 16;
constexpr int DHc = 64;
constexpr int FFc = 4096;
constexpr int BS  = Bc * Sc;
constexpr float LN_EPS = 1e-5f;

// ---------------------------------------------------------------------------
// Scratch (device globals; allocation is forbidden)
// ---------------------------------------------------------------------------
__device__ float g_zd[BS * Dc];
__device__ float g_x [BS * Dc];

__device__ __nv_bfloat16 g_maskb[(size_t)Sc*Sc];          // bf16 mask (range-safe)

// fp16 path
__device__ __half g_qi16[BS*Dc];                          // q input single fp16
__device__ __half g_ki16[BS*Dc];
__device__ __half g_vi16[BS*Dc];
__device__ __half g_wq16[Dc*Dc], g_wk16[Dc*Dc], g_wv16[Dc*Dc], g_wd16[Dc*Dc];
__device__ __half g_w1h16[(size_t)FFc*Dc];                // [4096,1024] K-major
__device__ __half g_w2h16[(size_t)Dc*FFc];                // [1024,4096] K-major
__device__ __half g_qp16[BS*Dc];                          // Q proj (pre-scaled 0.125), single
__device__ __half g_kp16[BS*Dc];                          // K proj, single
__device__ __half g_vt16[BS*Dc];                          // V proj transposed [B, D, S], single
__device__ __half g_zh16[BS*Dc], g_zl16[BS*Dc];           // attn out, 2-term
__device__ __half g_xh16[BS*Dc], g_xl16[BS*Dc];           // LN1 out, 2-term
__device__ __half g_f1h16[(size_t)BS*FFc], g_f1l16[(size_t)BS*FFc];

// ---------------------------------------------------------------------------
// PTX helpers (legal on plain compute_103)
// ---------------------------------------------------------------------------
__device__ __forceinline__ uint32_t s2u(const void* p) {
    uint32_t a;
    asm("{ .reg .u64 t; cvta.to.shared.u64 t, %1; cvt.u32.u64 %0, t; }" : "=r"(a) : "l"(p));
    return a;
}
#define SWZ(x) ((x) ^ (((x) >> 3) & 0x70))
#define CPA16(dst, src) asm volatile("cp.async.cg.shared.global [%0], [%1], 16;" :: "r"(dst), "l"(src))
#define CPA_COMMIT()    asm volatile("cp.async.commit_group;" ::: "memory")
#define CPA_WAIT(n)     asm volatile("cp.async.wait_group %0;" :: "n"(n) : "memory")

__device__ __forceinline__ void ldsm4(uint32_t* r, uint32_t addr) {
    asm volatile("ldmatrix.sync.aligned.m8n8.x4.shared.b16 {%0,%1,%2,%3}, [%4];"
        : "=r"(r[0]), "=r"(r[1]), "=r"(r[2]), "=r"(r[3]) : "r"(addr));
}
__device__ __forceinline__ void mma16816h(float* c, const uint32_t* a, const uint32_t* b) {
    asm volatile("mma.sync.aligned.m16n8k16.row.col.f32.f16.f16.f32 "
        "{%0,%1,%2,%3}, {%4,%5,%6,%7}, {%8,%9}, {%0,%1,%2,%3};"
        : "+f"(c[0]), "+f"(c[1]), "+f"(c[2]), "+f"(c[3])
        : "r"(a[0]), "r"(a[1]), "r"(a[2]), "r"(a[3]), "r"(b[0]), "r"(b[1]));
}
__device__ __forceinline__ uint32_t packbf2(float lo, float hi) {
    uint32_t r;
    asm("cvt.rn.bf16x2.f32 %0, %1, %2;" : "=r"(r) : "f"(hi), "f"(lo));
    return r;
}
__device__ __forceinline__ uint32_t packh2(float lo, float hi) {
    uint32_t r;
    asm("cvt.rn.f16x2.f32 %0, %1, %2;" : "=r"(r) : "f"(hi), "f"(lo));
    return r;
}
__device__ __forceinline__ float h_round(float x) {
    return __half2float(__float2half_rn(x));
}

// ---------------------------------------------------------------------------
// fp16 HMMA GEMM: C[M,N] = A[M,K] @ B^T (B [N,K] K-major fp16).
// TERMS=1: A single fp16 (Ah). TERMS=2: A = Ah + Al, two MMAs per frag.
// 128x128 tile, double buffered. Stage = (TERMS+1)*16K.
// EPI: 0 fp32, 1 bias+fp32, 2 bias+relu+fp16split, 6 fp16 single,
//      7 fp16 single transposed [B,D,S], 8 scale0.125+fp16 single
// ---------------------------------------------------------------------------
template <int TERMS, int EPI>
__global__ void __launch_bounds__(256, 2)
hmma_gemm_h(const __half* __restrict__ Ah_, const __half* __restrict__ Al_, int lda,
            const __half* __restrict__ B_, int ldb,
            float* __restrict__ C_, __half* __restrict__ Ch_, __half* __restrict__ Cl_,
            int ldc, int K, const float* __restrict__ bias)
{
    constexpr int AOFF  = 16384;
    constexpr int BOFF  = TERMS * 16384;
    constexpr int STAGE = (TERMS + 1) * 16384;

    extern __shared__ __align__(1024) char smem[];
    const uint32_t sbase = s2u(smem);

    const int tid  = threadIdx.x;
    const int wid  = tid >> 5;
    const int lane = tid & 31;
    const int warp_m = wid & 1;
    const int warp_n = wid >> 1;

    const int m0 = blockIdx.y * 128;
    const int n0 = blockIdx.x * 128;
    const int NC = K >> 6;

    float acc[4][4][4];
    #pragma unroll
    for (int i = 0; i < 4; i++)
        #pragma unroll
        for (int j = 0; j < 4; j++)
            #pragma unroll
            for (int e = 0; e < 4; e++) acc[i][j][e] = 0.f;

    auto load_chunk = [&](int c, int s) {
        const uint32_t s0 = sbase + s * STAGE;
        const int kk = c * 64;
        #pragma unroll
        for (int i = 0; i < 4; i++) {
            const int e = tid + i * 256;
            const int row = e >> 3, c16 = e & 7;
            const uint32_t off = SWZ(row * 128 + c16 * 16);
            const size_t go = (size_t)(m0 + row) * lda + kk + c16 * 8;
            CPA16(s0 + off, Ah_ + go);
            if (TERMS == 2) CPA16(s0 + AOFF + off, Al_ + go);
        }
        #pragma unroll
        for (int i = 0; i < 4; i++) {
            const int e = tid + i * 256;
            const int row = e >> 3, c16 = e & 7;
            const uint32_t off = SWZ(row * 128 + c16 * 16);
            CPA16(s0 + BOFF + off, B_ + (size_t)(n0 + row) * ldb + kk + c16 * 8);
        }
    };

    load_chunk(0, 0); CPA_COMMIT();
    if (NC > 1) { load_chunk(1, 1); CPA_COMMIT(); }

    const int a_r = lane & 15;
    const int a_k = (lane >> 4) & 1;
    const int b_r = lane & 7;
    const int b_k = (lane >> 3) & 1;
    const int b_n = (lane >> 4) & 1;

    for (int c = 0; c < NC; c++) {
        if (c + 1 < NC) { CPA_WAIT(1); } else { CPA_WAIT(0); }
        __syncthreads();
        const uint32_t s0 = sbase + (c & 1) * STAGE;

        #pragma unroll
        for (int ks = 0; ks < 4; ks++) {
            uint32_t bh[8];
            #pragma unroll
            for (int j2 = 0; j2 < 2; j2++) {
                const uint32_t off = SWZ((warp_n * 32 + j2 * 16 + b_n * 8 + b_r) * 128 + ks * 32 + b_k * 16);
                ldsm4(&bh[j2 * 4], s0 + BOFF + off);
            }
            #pragma unroll
            for (int im = 0; im < 4; im++) {
                uint32_t ah[4], al[4];
                const uint32_t off = SWZ((warp_m * 64 + im * 16 + a_r) * 128 + ks * 32 + a_k * 16);
                ldsm4(ah, s0 + off);
                if (TERMS == 2) ldsm4(al, s0 + AOFF + off);
                #pragma unroll
                for (int jn = 0; jn < 4; jn++) {
                    mma16816h(acc[im][jn], ah, &bh[jn * 2]);
                    if (TERMS == 2) mma16816h(acc[im][jn], al, &bh[jn * 2]);
                }
            }
        }
        __syncthreads();
        if (c + 2 < NC) { load_chunk(c + 2, c & 1); CPA_COMMIT(); }
    }

    const int qr = lane >> 2;
    const int qc = (lane & 3) * 2;
    #pragma unroll
    for (int im = 0; im < 4; im++) {
        const int m = m0 + warp_m * 64 + im * 16 + qr;
        #pragma unroll
        for (int jn = 0; jn < 4; jn++) {
            const int n = n0 + warp_n * 32 + jn * 8 + qc;
            float2 v0 = make_float2(acc[im][jn][0], acc[im][jn][1]);
            float2 v1 = make_float2(acc[im][jn][2], acc[im][jn][3]);
            if (EPI == 1 || EPI == 2) {
                const float2 bv = *reinterpret_cast<const float2*>(bias + n);
                v0.x += bv.x; v0.y += bv.y; v1.x += bv.x; v1.y += bv.y;
            }
            if (EPI == 8) {
                v0.x *= 0.125f; v0.y *= 0.125f; v1.x *= 0.125f; v1.y *= 0.125f;
            }
            if (EPI == 2) {
                v0.x = fmaxf(v0.x, 0.f); v0.y = fmaxf(v0.y, 0.f);
                v1.x = fmaxf(v1.x, 0.f); v1.y = fmaxf(v1.y, 0.f);
            }
            if (EPI == 2) {
                *reinterpret_cast<uint32_t*>(Ch_ + (size_t)m * ldc + n)       = packh2(v0.x, v0.y);
                *reinterpret_cast<uint32_t*>(Ch_ + (size_t)(m + 8) * ldc + n) = packh2(v1.x, v1.y);
                *reinterpret_cast<uint32_t*>(Cl_ + (size_t)m * ldc + n)       =
                    packh2(v0.x - h_round(v0.x), v0.y - h_round(v0.y));
                *reinterpret_cast<uint32_t*>(Cl_ + (size_t)(m + 8) * ldc + n) =
                    packh2(v1.x - h_round(v1.x), v1.y - h_round(v1.y));
            } else if (EPI == 6 || EPI == 8) {
                *reinterpret_cast<uint32_t*>(Ch_ + (size_t)m * ldc + n)       = packh2(v0.x, v0.y);
                *reinterpret_cast<uint32_t*>(Ch_ + (size_t)(m + 8) * ldc + n) = packh2(v1.x, v1.y);
            } else if (EPI == 7) {
                // transposed per-batch: out[b, n, s] ; batch = m>>11, s = m&2047
                const size_t base = (size_t)(m >> 11) * Dc * Sc;
                const int s_ = m & 2047;
                Ch_[base + (size_t)n * Sc + s_]           = __float2half_rn(v0.x);
                Ch_[base + (size_t)(n + 1) * Sc + s_]     = __float2half_rn(v0.y);
                Ch_[base + (size_t)n * Sc + s_ + 8]       = __float2half_rn(v1.x);
                Ch_[base + (size_t)(n + 1) * Sc + s_ + 8] = __float2half_rn(v1.y);
            } else {
                *reinterpret_cast<float2*>(C_ + (size_t)m * ldc + n)       = v0;
                *reinterpret_cast<float2*>(C_ + (size_t)(m + 8) * ldc + n) = v1;
            }
        }
    }
}

// ---------------------------------------------------------------------------
// Fused FlashAttention, single-fp16 Q/K/V/P (Q pre-scaled 0.125)
// Q [S,D], K [S,D], V^T [B,D,S]; z out fp16 hi/lo [S,D] merged heads.
// smem: Q 16K + 2 stages x (K 16K + V 16K) = 80K.
// ---------------------------------------------------------------------------
__global__ void __launch_bounds__(256)
fa_kernel(const __half* __restrict__ q_,
          const __half* __restrict__ k_,
          const __half* __restrict__ vt_,
          const __nv_bfloat16* __restrict__ maskb,
          __half* __restrict__ zh, __half* __restrict__ zl)
{
    constexpr int QH = 0;
    constexpr int ST0 = 16384, STB = 32768;
    constexpr int KHo = 0, VHo = 16384;
    constexpr int NT = Sc / 128;

    extern __shared__ __align__(1024) char smem[];
    const uint32_t sbase = s2u(smem);

    const int tid  = threadIdx.x;
    const int wid  = tid >> 5;
    const int lane = tid & 31;

    const int z = blockIdx.y;
    const int b = z >> 4, h = z & 15;
    const int m0 = blockIdx.x * 128;

    const __half* Qp = q_  + ((size_t)(b * Sc + m0)) * Dc + h * DHc;
    const __half* Kp = k_  + (size_t)b * Sc * Dc + h * DHc;
    const __half* Vp = vt_ + ((size_t)b * Dc + h * DHc) * Sc;

    #pragma unroll
    for (int i = 0; i < 4; i++) {
        const int e = tid + i * 256;
        const int row = e >> 3, c16 = e & 7;
        const uint32_t off = SWZ(row * 128 + c16 * 16);
        CPA16(sbase + QH + off, Qp + (size_t)row * Dc + c16 * 8);
    }
    auto load_kv = [&](int kt, int s) {
        const uint32_t s0 = sbase + ST0 + s * STB;
        #pragma unroll
        for (int i = 0; i < 4; i++) {
            const int e = tid + i * 256;
            const int row = e >> 3, c16 = e & 7;
            const uint32_t off = SWZ(row * 128 + c16 * 16);
            CPA16(s0 + KHo + off, Kp + (size_t)(kt * 128 + row) * Dc + c16 * 8);
        }
        #pragma unroll
        for (int i = 0; i < 4; i++) {
            const int e = tid + i * 256;
            const int row = e >> 4, c16 = e & 15;
            const uint32_t off = SWZ(row * 256 + c16 * 16);
            CPA16(s0 + VHo + off, Vp + (size_t)row * Sc + kt * 128 + c16 * 8);
        }
    };
    load_kv(0, 0); CPA_COMMIT();
    load_kv(1, 1); CPA_COMMIT();

    const int a_r = lane & 15;
    const int a_k = (lane >> 4) & 1;
    const int b_r = lane & 7;
    const int b_k = (lane >> 3) & 1;
    const int b_n = (lane >> 4) & 1;
    const int qr  = lane >> 2;
    const int qc  = (lane & 3) * 2;

    float O[8][4];
    #pragma unroll
    for (int j = 0; j < 8; j++)
        #pragma unroll
        for (int e = 0; e < 4; e++) O[j][e] = 0.f;
    float pm0 = -1e30f, pm1 = -1e30f, l0 = 0.f, l1 = 0.f;

    const int row0 = m0 + wid * 16 + qr;
    const __nv_bfloat16* mrow0 = maskb + (size_t)row0 * Sc;
    const __nv_bfloat16* mrow1 = maskb + (size_t)(row0 + 8) * Sc;

    for (int kt = 0; kt < NT; kt++) {
        if (kt + 1 < NT) { CPA_WAIT(1); } else { CPA_WAIT(0); }
        __syncthreads();
        const uint32_t s0 = sbase + ST0 + (kt & 1) * STB;

        float s[16][4];
        #pragma unroll
        for (int j = 0; j < 16; j++)
            #pragma unroll
            for (int e = 0; e < 4; e++) s[j][e] = 0.f;

        #pragma unroll
        for (int ks = 0; ks < 4; ks++) {
            uint32_t ah[4];
            {
                const uint32_t off = SWZ((wid * 16 + a_r) * 128 + ks * 32 + a_k * 16);
                ldsm4(ah, sbase + QH + off);
            }
            #pragma unroll
            for (int j2 = 0; j2 < 8; j2++) {
                uint32_t bh[4];
                const uint32_t off = SWZ((j2 * 16 + b_n * 8 + b_r) * 128 + ks * 32 + b_k * 16);
                ldsm4(bh, s0 + KHo + off);
                mma16816h(s[j2 * 2],     ah, bh);
                mma16816h(s[j2 * 2 + 1], ah, bh + 2);
            }
        }

        float mx0 = -1e30f, mx1 = -1e30f;
        #pragma unroll
        for (int jn = 0; jn < 16; jn++) {
            const int col = kt * 128 + jn * 8 + qc;
            const float2 mv0 = __bfloat1622float2(
                *reinterpret_cast<const __nv_bfloat162*>(mrow0 + col));
            const float2 mv1 = __bfloat1622float2(
                *reinterpret_cast<const __nv_bfloat162*>(mrow1 + col));
            s[jn][0] += mv0.x;
            s[jn][1] += mv0.y;
            s[jn][2] += mv1.x;
            s[jn][3] += mv1.y;
            mx0 = fmaxf(mx0, fmaxf(s[jn][0], s[jn][1]));
            mx1 = fmaxf(mx1, fmaxf(s[jn][2], s[jn][3]));
        }
        mx0 = fmaxf(mx0, __shfl_xor_sync(0xffffffffu, mx0, 1));
        mx0 = fmaxf(mx0, __shfl_xor_sync(0xffffffffu, mx0, 2));
        mx1 = fmaxf(mx1, __shfl_xor_sync(0xffffffffu, mx1, 1));
        mx1 = fmaxf(mx1, __shfl_xor_sync(0xffffffffu, mx1, 2));
        const float nm0 = fmaxf(pm0, mx0), nm1 = fmaxf(pm1, mx1);
        const float sc0 = __expf(pm0 - nm0), sc1 = __expf(pm1 - nm1);
        l0 *= sc0; l1 *= sc1;
        #pragma unroll
        for (int j = 0; j < 8; j++) {
            O[j][0] *= sc0; O[j][1] *= sc0; O[j][2] *= sc1; O[j][3] *= sc1;
        }
        float sum0 = 0.f, sum1 = 0.f;
        #pragma unroll
        for (int jn = 0; jn < 16; jn++) {
            s[jn][0] = __expf(s[jn][0] - nm0);
            s[jn][1] = __expf(s[jn][1] - nm0);
            s[jn][2] = __expf(s[jn][2] - nm1);
            s[jn][3] = __expf(s[jn][3] - nm1);
            sum0 += s[jn][0] + s[jn][1];
            sum1 += s[jn][2] + s[jn][3];
        }
        sum0 += __shfl_xor_sync(0xffffffffu, sum0, 1);
        sum0 += __shfl_xor_sync(0xffffffffu, sum0, 2);
        sum1 += __shfl_xor_sync(0xffffffffu, sum1, 1);
        sum1 += __shfl_xor_sync(0xffffffffu, sum1, 2);
        l0 += sum0; l1 += sum1;
        pm0 = nm0; pm1 = nm1;

        #pragma unroll
        for (int ks2 = 0; ks2 < 8; ks2++) {
            uint32_t ph[4];
            ph[0] = packh2(s[2 * ks2][0],     s[2 * ks2][1]);
            ph[1] = packh2(s[2 * ks2][2],     s[2 * ks2][3]);
            ph[2] = packh2(s[2 * ks2 + 1][0], s[2 * ks2 + 1][1]);
            ph[3] = packh2(s[2 * ks2 + 1][2], s[2 * ks2 + 1][3]);
            #pragma unroll
            for (int j2 = 0; j2 < 4; j2++) {
                uint32_t vh2[4];
                const uint32_t off = SWZ((j2 * 16 + b_n * 8 + b_r) * 256 + ks2 * 32 + b_k * 16);
                ldsm4(vh2, s0 + VHo + off);
                mma16816h(O[j2 * 2],     ph, vh2);
                mma16816h(O[j2 * 2 + 1], ph, vh2 + 2);
            }
        }

        __syncthreads();
        if (kt + 2 < NT) { load_kv(kt + 2, kt & 1); CPA_COMMIT(); }
    }

    const float inv0 = 1.0f / l0, inv1 = 1.0f / l1;
    const size_t r0 = (size_t)(b * Sc + row0) * Dc + h * DHc;
    const size_t r1 = r0 + 8 * Dc;
    #pragma unroll
    for (int jn = 0; jn < 8; jn++) {
        const int n = jn * 8 + qc;
        const float a = O[jn][0] * inv0, bb = O[jn][1] * inv0;
        const float c = O[jn][2] * inv1, d  = O[jn][3] * inv1;
        *reinterpret_cast<uint32_t*>(zh + r0 + n) = packh2(a, bb);
        *reinterpret_cast<uint32_t*>(zl + r0 + n) = packh2(a - h_round(a), bb - h_round(bb));
        *reinterpret_cast<uint32_t*>(zh + r1 + n) = packh2(c, d);
        *reinterpret_cast<uint32_t*>(zl + r1 + n) = packh2(c - h_round(c), d - h_round(d));
    }
}

// ---------------------------------------------------------------------------
// Elementwise helpers
// ---------------------------------------------------------------------------
__global__ void __launch_bounds__(256)
cvt_h_kernel(const float* __restrict__ x, __half* __restrict__ h, long long n)
{
    const long long i = ((long long)blockIdx.x * 256 + threadIdx.x) * 4;
    if (i >= n) return;
    const float4 v = *reinterpret_cast<const float4*>(x + i);
    uint32_t* hp = reinterpret_cast<uint32_t*>(h + i);
    hp[0] = packh2(v.x, v.y); hp[1] = packh2(v.z, v.w);
}

__global__ void __launch_bounds__(256)
maskbf_kernel(const float* __restrict__ m, __nv_bfloat16* __restrict__ o, long long n)
{
    const long long i = ((long long)blockIdx.x * 256 + threadIdx.x) * 4;
    if (i >= n) return;
    const float4 v = *reinterpret_cast<const float4*>(m + i);
    uint32_t* op = reinterpret_cast<uint32_t*>(o + i);
    op[0] = packbf2(v.x, v.y); op[1] = packbf2(v.z, v.w);
}

// transpose fp32 [R, C] -> fp16 [C, R] (weights, single precision)
__global__ void __launch_bounds__(256)
tsplit_h_kernel(const float* __restrict__ in, __half* __restrict__ oh, int R, int Ccols)
{
    __shared__ float t[32][33];
    const int c0 = blockIdx.x * 32, r0 = blockIdx.y * 32;
    const int tx = threadIdx.x & 31, ty = threadIdx.x >> 5;
    #pragma unroll
    for (int i = 0; i < 32; i += 8)
        t[ty + i][tx] = in[(size_t)(r0 + ty + i) * Ccols + c0 + tx];
    __syncthreads();
    #pragma unroll
    for (int i = 0; i < 32; i += 8)
        oh[(size_t)(c0 + ty + i) * R + r0 + tx] = __float2half_rn(t[tx][ty + i]);
}

// ---------------------------------------------------------------------------
// LayerNorm (+ residual); SPLIT writes fp16 hi/lo side-output
// ---------------------------------------------------------------------------
template <bool ADD_FIRST, bool SPLIT>
__global__ void __launch_bounds__(256)
ln_kernel(const float* __restrict__ a, const float* __restrict__ r,
          const float* __restrict__ g, const float* __restrict__ be,
          float* __restrict__ out, __half* __restrict__ oh, __half* __restrict__ ol)
{
    __shared__ float rs[8], rs2[8];
    const size_t base = (size_t)blockIdx.x * Dc;
    const int tid = threadIdx.x;
    float v[4];
    float s = 0.f, s2 = 0.f;
    #pragma unroll
    for (int j = 0; j < 4; j++) {
        const int c = tid + j * 256;
        float t = a[base + c];
        if (ADD_FIRST) t += r[base + c];
        v[j] = t; s += t; s2 += t * t;
    }
    #pragma unroll
    for (int o = 16; o; o >>= 1) {
        s  += __shfl_xor_sync(0xffffffffu, s, o);
        s2 += __shfl_xor_sync(0xffffffffu, s2, o);
    }
    if ((tid & 31) == 0) { rs[tid >> 5] = s; rs2[tid >> 5] = s2; }
    __syncthreads();
    if (tid == 0) {
        float t = 0.f, t2 = 0.f;
        for (int i = 0; i < 8; i++) { t += rs[i]; t2 += rs2[i]; }
        rs[0] = t; rs2[0] = t2;
    }
    __syncthreads();
    const float mu   = rs[0] * (1.0f / Dc);
    const float var  = rs2[0] * (1.0f / Dc) - mu * mu;
    const float rstd = rsqrtf(var + LN_EPS);
    #pragma unroll
    for (int j = 0; j < 4; j++) {
        const int c = tid + j * 256;
        float o = (v[j] - mu) * rstd * g[c] + be[c];
        if (!ADD_FIRST) o += r[base + c];
        out[base + c] = o;
        if (SPLIT) {
            const __half hb = __float2half_rn(o);
            oh[base + c] = hb;
            ol[base + c] = __float2half_rn(o - __half2float(hb));
        }
    }
}

// ---------------------------------------------------------------------------
// Launch
// ---------------------------------------------------------------------------
extern "C" void kernel_launch(void* const* d_in, const int* in_sizes, int n_in,
                              void* d_out, int out_size)
{
    (void)in_sizes; (void)n_in; (void)out_size;

    const float* q    = (const float*)d_in[0];
    const float* k    = (const float*)d_in[1];
    const float* v    = (const float*)d_in[2];
    const float* mask = (const float*)d_in[4];
    const float* Wq   = (const float*)d_in[5];
    const float* Wk   = (const float*)d_in[6];
    const float* Wv   = (const float*)d_in[7];
    const float* Wd   = (const float*)d_in[8];
    const float* W1   = (const float*)d_in[9];
    const float* b1   = (const float*)d_in[10];
    const float* W2   = (const float*)d_in[11];
    const float* b2   = (const float*)d_in[12];
    const float* g1   = (const float*)d_in[13];
    const float* be1  = (const float*)d_in[14];
    const float* g2   = (const float*)d_in[15];
    const float* be2  = (const float*)d_in[16];
    float* out = (float*)d_out;

    float *zd, *x;
    cudaGetSymbolAddress((void**)&zd, g_zd);
    cudaGetSymbolAddress((void**)&x,  g_x);

    __nv_bfloat16 *maskb;
    __half *qi16,*ki16,*vi16,*wq16,*wk16,*wv16,*wd16,*w1h16,*w2h16;
    __half *qp16,*kp16,*vt16,*zh16,*zl16,*xh16,*xl16,*f1h16,*f1l16;
    cudaGetSymbolAddress((void**)&maskb, g_maskb);
    cudaGetSymbolAddress((void**)&qi16, g_qi16);
    cudaGetSymbolAddress((void**)&ki16, g_ki16);
    cudaGetSymbolAddress((void**)&vi16, g_vi16);
    cudaGetSymbolAddress((void**)&wq16, g_wq16); cudaGetSymbolAddress((void**)&wk16, g_wk16);
    cudaGetSymbolAddress((void**)&wv16, g_wv16); cudaGetSymbolAddress((void**)&wd16, g_wd16);
    cudaGetSymbolAddress((void**)&w1h16, g_w1h16); cudaGetSymbolAddress((void**)&w2h16, g_w2h16);
    cudaGetSymbolAddress((void**)&qp16, g_qp16);
    cudaGetSymbolAddress((void**)&kp16, g_kp16); cudaGetSymbolAddress((void**)&vt16, g_vt16);
    cudaGetSymbolAddress((void**)&zh16, g_zh16); cudaGetSymbolAddress((void**)&zl16, g_zl16);
    cudaGetSymbolAddress((void**)&xh16, g_xh16); cudaGetSymbolAddress((void**)&xl16, g_xl16);
    cudaGetSymbolAddress((void**)&f1h16, g_f1h16); cudaGetSymbolAddress((void**)&f1l16, g_f1l16);

    constexpr int SMEM_1 = 2 * 32768;           //  65536 (1-term A GEMM)
    constexpr int SMEM_2 = 2 * 49152;           //  98304 (2-term A GEMM)
    constexpr int SMEM_FA = 16384 + 2 * 32768;  //  81920 (FA)
    cudaFuncSetAttribute(hmma_gemm_h<1, 6>, cudaFuncAttributeMaxDynamicSharedMemorySize, SMEM_1);
    cudaFuncSetAttribute(hmma_gemm_h<1, 7>, cudaFuncAttributeMaxDynamicSharedMemorySize, SMEM_1);
    cudaFuncSetAttribute(hmma_gemm_h<1, 8>, cudaFuncAttributeMaxDynamicSharedMemorySize, SMEM_1);
    cudaFuncSetAttribute(hmma_gemm_h<2, 0>, cudaFuncAttributeMaxDynamicSharedMemorySize, SMEM_2);
    cudaFuncSetAttribute(hmma_gemm_h<2, 1>, cudaFuncAttributeMaxDynamicSharedMemorySize, SMEM_2);
    cudaFuncSetAttribute(hmma_gemm_h<2, 2>, cudaFuncAttributeMaxDynamicSharedMemorySize, SMEM_2);
    cudaFuncSetAttribute(fa_kernel, cudaFuncAttributeMaxDynamicSharedMemorySize, SMEM_FA);

    const dim3 b256(256);

    // ---- weight transpose (fp16 single) ----
    tsplit_h_kernel<<<dim3(32, 32, 1),  b256>>>(Wq, wq16, Dc, Dc);
    tsplit_h_kernel<<<dim3(32, 32, 1),  b256>>>(Wk, wk16, Dc, Dc);
    tsplit_h_kernel<<<dim3(32, 32, 1),  b256>>>(Wv, wv16, Dc, Dc);
    tsplit_h_kernel<<<dim3(32, 32, 1),  b256>>>(Wd, wd16, Dc, Dc);
    tsplit_h_kernel<<<dim3(128, 32, 1), b256>>>(W1, w1h16, Dc, FFc);
    tsplit_h_kernel<<<dim3(32, 128, 1), b256>>>(W2, w2h16, FFc, Dc);

    // ---- mask -> bf16 ----
    maskbf_kernel<<<(unsigned)((long long)Sc * Sc / 1024), b256>>>(
        mask, maskb, (long long)Sc * Sc);

    // ---- input converts (single fp16) ----
    const long long nBD = (long long)BS * Dc;
    cvt_h_kernel<<<(unsigned)(nBD / 1024), b256>>>(q, qi16, nBD);
    cvt_h_kernel<<<(unsigned)(nBD / 1024), b256>>>(k, ki16, nBD);
    cvt_h_kernel<<<(unsigned)(nBD / 1024), b256>>>(v, vi16, nBD);

    // ---- QKV projections (1-term A, single fp16 weights) ----
    hmma_gemm_h<1, 8><<<dim3(8, 32, 1), b256, SMEM_1>>>(     // Q: x0.125, single out
        qi16, nullptr, Dc, wq16, Dc, nullptr, qp16, nullptr, Dc, Dc, nullptr);
    hmma_gemm_h<1, 6><<<dim3(8, 32, 1), b256, SMEM_1>>>(     // K: single out
        ki16, nullptr, Dc, wk16, Dc, nullptr, kp16, nullptr, Dc, Dc, nullptr);
    hmma_gemm_h<1, 7><<<dim3(8, 32, 1), b256, SMEM_1>>>(     // V: single out, transposed
        vi16, nullptr, Dc, wv16, Dc, nullptr, vt16, nullptr, 0, Dc, nullptr);

    // ---- fused flash attention -> zh/zl (2-term out) ----
    fa_kernel<<<dim3(Sc / 128, Bc * Hc), b256, SMEM_FA>>>(
        qp16, kp16, vt16, maskb, zh16, zl16);

    // ---- zd = z @ Wd (2-term A) ----
    hmma_gemm_h<2, 0><<<dim3(8, 32, 1), b256, SMEM_2>>>(
        zh16, zl16, Dc, wd16, Dc, zd, nullptr, nullptr, Dc, Dc, nullptr);

    // ---- x = LN(zd)*g1 + be1 + q  (+ fp16 2-term split) ----
    ln_kernel<false, true><<<BS, b256>>>(zd, q, g1, be1, x, xh16, xl16);

    // ---- FFN (2-term A) ----
    hmma_gemm_h<2, 2><<<dim3(32, 32, 1), b256, SMEM_2>>>(
        xh16, xl16, Dc, w1h16, Dc, nullptr, f1h16, f1l16, FFc, Dc, b1);
    hmma_gemm_h<2, 1><<<dim3(8, 32, 1), b256, SMEM_2>>>(
        f1h16, f1l16, FFc, w2h16, FFc, zd, nullptr, nullptr, Dc, FFc, b2);

    // ---- out = LN(ff2 + x)*g2 + be2 ----
    ln_kernel<true, false><<<BS, b256>>>(zd, x, g2, be2, out, nullptr, nullptr);
}

// round 17
// speedup vs baseline: 1.8096x; 1.2944x over previous
#include <cuda_runtime.h>
#include <cuda_bf16.h>
#include <cuda_fp16.h>
#include <cstdint>

// ---------------------------------------------------------------------------
// Problem constants
// ---------------------------------------------------------------------------
constexpr int Bc  = 2;
constexpr int Sc  = 2048;
constexpr int Dc  = 1024;
constexpr int Hc  = 16;
constexpr int DHc = 64;
constexpr int FFc = 4096;
constexpr int BS  = Bc * Sc;
constexpr float LN_EPS = 1e-5f;

// ---------------------------------------------------------------------------
// Scratch (device globals; allocation is forbidden)
// ---------------------------------------------------------------------------
__device__ float g_zd[BS * Dc];
__device__ float g_x [BS * Dc];

__device__ __nv_bfloat16 g_maskb[(size_t)Sc*Sc];          // bf16 mask (range-safe)

// fp16 path (all single precision streams)
__device__ __half g_qi16[BS*Dc];
__device__ __half g_ki16[BS*Dc];
__device__ __half g_vi16[BS*Dc];
__device__ __half g_wq16[Dc*Dc], g_wk16[Dc*Dc], g_wv16[Dc*Dc], g_wd16[Dc*Dc];
__device__ __half g_w1h16[(size_t)FFc*Dc];                // [4096,1024] K-major
__device__ __half g_w2h16[(size_t)Dc*FFc];                // [1024,4096] K-major
__device__ __half g_qp16[BS*Dc];                          // Q proj (pre-scaled 0.125)
__device__ __half g_kp16[BS*Dc];                          // K proj
__device__ __half g_vt16[BS*Dc];                          // V proj transposed [B, D, S]
__device__ __half g_z16[BS*Dc];                           // attn out
__device__ __half g_x16[BS*Dc];                           // LN1 out
__device__ __half g_f116[(size_t)BS*FFc];                 // relu(FFN1)

// ---------------------------------------------------------------------------
// PTX helpers (legal on plain compute_103)
// ---------------------------------------------------------------------------
__device__ __forceinline__ uint32_t s2u(const void* p) {
    uint32_t a;
    asm("{ .reg .u64 t; cvta.to.shared.u64 t, %1; cvt.u32.u64 %0, t; }" : "=r"(a) : "l"(p));
    return a;
}
#define SWZ(x) ((x) ^ (((x) >> 3) & 0x70))
#define CPA16(dst, src) asm volatile("cp.async.cg.shared.global [%0], [%1], 16;" :: "r"(dst), "l"(src))
#define CPA_COMMIT()    asm volatile("cp.async.commit_group;" ::: "memory")
#define CPA_WAIT(n)     asm volatile("cp.async.wait_group %0;" :: "n"(n) : "memory")

__device__ __forceinline__ void ldsm4(uint32_t* r, uint32_t addr) {
    asm volatile("ldmatrix.sync.aligned.m8n8.x4.shared.b16 {%0,%1,%2,%3}, [%4];"
        : "=r"(r[0]), "=r"(r[1]), "=r"(r[2]), "=r"(r[3]) : "r"(addr));
}
__device__ __forceinline__ void mma16816h(float* c, const uint32_t* a, const uint32_t* b) {
    asm volatile("mma.sync.aligned.m16n8k16.row.col.f32.f16.f16.f32 "
        "{%0,%1,%2,%3}, {%4,%5,%6,%7}, {%8,%9}, {%0,%1,%2,%3};"
        : "+f"(c[0]), "+f"(c[1]), "+f"(c[2]), "+f"(c[3])
        : "r"(a[0]), "r"(a[1]), "r"(a[2]), "r"(a[3]), "r"(b[0]), "r"(b[1]));
}
__device__ __forceinline__ uint32_t packbf2(float lo, float hi) {
    uint32_t r;
    asm("cvt.rn.bf16x2.f32 %0, %1, %2;" : "=r"(r) : "f"(hi), "f"(lo));
    return r;
}
__device__ __forceinline__ uint32_t packh2(float lo, float hi) {
    uint32_t r;
    asm("cvt.rn.f16x2.f32 %0, %1, %2;" : "=r"(r) : "f"(hi), "f"(lo));
    return r;
}
__device__ __forceinline__ float h_round(float x) {
    return __half2float(__float2half_rn(x));
}

// ---------------------------------------------------------------------------
// fp16 HMMA GEMM (1-term A): C[M,N] = A[M,K] @ B^T (B [N,K] K-major fp16).
// 128x128 tile, double buffered. Stage 32K; 2 stages = 64K -> 2 CTAs/SM.
// EPI: 0 fp32, 1 bias+fp32, 2 bias+relu+fp16, 6 fp16,
//      7 fp16 transposed [B,D,S], 8 scale0.125+fp16
// ---------------------------------------------------------------------------
template <int EPI>
__global__ void __launch_bounds__(256, 2)
hmma_gemm_h(const __half* __restrict__ A_, int lda,
            const __half* __restrict__ B_, int ldb,
            float* __restrict__ C_, __half* __restrict__ Ch_,
            int ldc, int K, const float* __restrict__ bias)
{
    constexpr int BOFF  = 16384;
    constexpr int STAGE = 32768;

    extern __shared__ __align__(1024) char smem[];
    const uint32_t sbase = s2u(smem);

    const int tid  = threadIdx.x;
    const int wid  = tid >> 5;
    const int lane = tid & 31;
    const int warp_m = wid & 1;
    const int warp_n = wid >> 1;

    const int m0 = blockIdx.y * 128;
    const int n0 = blockIdx.x * 128;
    const int NC = K >> 6;

    float acc[4][4][4];
    #pragma unroll
    for (int i = 0; i < 4; i++)
        #pragma unroll
        for (int j = 0; j < 4; j++)
            #pragma unroll
            for (int e = 0; e < 4; e++) acc[i][j][e] = 0.f;

    auto load_chunk = [&](int c, int s) {
        const uint32_t s0 = sbase + s * STAGE;
        const int kk = c * 64;
        #pragma unroll
        for (int i = 0; i < 4; i++) {
            const int e = tid + i * 256;
            const int row = e >> 3, c16 = e & 7;
            const uint32_t off = SWZ(row * 128 + c16 * 16);
            CPA16(s0 + off, A_ + (size_t)(m0 + row) * lda + kk + c16 * 8);
        }
        #pragma unroll
        for (int i = 0; i < 4; i++) {
            const int e = tid + i * 256;
            const int row = e >> 3, c16 = e & 7;
            const uint32_t off = SWZ(row * 128 + c16 * 16);
            CPA16(s0 + BOFF + off, B_ + (size_t)(n0 + row) * ldb + kk + c16 * 8);
        }
    };

    load_chunk(0, 0); CPA_COMMIT();
    if (NC > 1) { load_chunk(1, 1); CPA_COMMIT(); }

    const int a_r = lane & 15;
    const int a_k = (lane >> 4) & 1;
    const int b_r = lane & 7;
    const int b_k = (lane >> 3) & 1;
    const int b_n = (lane >> 4) & 1;

    for (int c = 0; c < NC; c++) {
        if (c + 1 < NC) { CPA_WAIT(1); } else { CPA_WAIT(0); }
        __syncthreads();
        const uint32_t s0 = sbase + (c & 1) * STAGE;

        #pragma unroll
        for (int ks = 0; ks < 4; ks++) {
            uint32_t bh[8];
            #pragma unroll
            for (int j2 = 0; j2 < 2; j2++) {
                const uint32_t off = SWZ((warp_n * 32 + j2 * 16 + b_n * 8 + b_r) * 128 + ks * 32 + b_k * 16);
                ldsm4(&bh[j2 * 4], s0 + BOFF + off);
            }
            #pragma unroll
            for (int im = 0; im < 4; im++) {
                uint32_t ah[4];
                const uint32_t off = SWZ((warp_m * 64 + im * 16 + a_r) * 128 + ks * 32 + a_k * 16);
                ldsm4(ah, s0 + off);
                #pragma unroll
                for (int jn = 0; jn < 4; jn++)
                    mma16816h(acc[im][jn], ah, &bh[jn * 2]);
            }
        }
        __syncthreads();
        if (c + 2 < NC) { load_chunk(c + 2, c & 1); CPA_COMMIT(); }
    }

    const int qr = lane >> 2;
    const int qc = (lane & 3) * 2;
    #pragma unroll
    for (int im = 0; im < 4; im++) {
        const int m = m0 + warp_m * 64 + im * 16 + qr;
        #pragma unroll
        for (int jn = 0; jn < 4; jn++) {
            const int n = n0 + warp_n * 32 + jn * 8 + qc;
            float2 v0 = make_float2(acc[im][jn][0], acc[im][jn][1]);
            float2 v1 = make_float2(acc[im][jn][2], acc[im][jn][3]);
            if (EPI == 1 || EPI == 2) {
                const float2 bv = *reinterpret_cast<const float2*>(bias + n);
                v0.x += bv.x; v0.y += bv.y; v1.x += bv.x; v1.y += bv.y;
            }
            if (EPI == 8) {
                v0.x *= 0.125f; v0.y *= 0.125f; v1.x *= 0.125f; v1.y *= 0.125f;
            }
            if (EPI == 2) {
                v0.x = fmaxf(v0.x, 0.f); v0.y = fmaxf(v0.y, 0.f);
                v1.x = fmaxf(v1.x, 0.f); v1.y = fmaxf(v1.y, 0.f);
            }
            if (EPI == 2 || EPI == 6 || EPI == 8) {
                *reinterpret_cast<uint32_t*>(Ch_ + (size_t)m * ldc + n)       = packh2(v0.x, v0.y);
                *reinterpret_cast<uint32_t*>(Ch_ + (size_t)(m + 8) * ldc + n) = packh2(v1.x, v1.y);
            } else if (EPI == 7) {
                // transposed per-batch: out[b, n, s] ; batch = m>>11, s = m&2047
                const size_t base = (size_t)(m >> 11) * Dc * Sc;
                const int s_ = m & 2047;
                Ch_[base + (size_t)n * Sc + s_]           = __float2half_rn(v0.x);
                Ch_[base + (size_t)(n + 1) * Sc + s_]     = __float2half_rn(v0.y);
                Ch_[base + (size_t)n * Sc + s_ + 8]       = __float2half_rn(v1.x);
                Ch_[base + (size_t)(n + 1) * Sc + s_ + 8] = __float2half_rn(v1.y);
            } else {
                *reinterpret_cast<float2*>(C_ + (size_t)m * ldc + n)       = v0;
                *reinterpret_cast<float2*>(C_ + (size_t)(m + 8) * ldc + n) = v1;
            }
        }
    }
}

// ---------------------------------------------------------------------------
// Fused FlashAttention, single-fp16 Q/K/V/P (Q pre-scaled 0.125)
// Q [S,D], K [S,D], V^T [B,D,S]; z out single fp16 [S,D] merged heads.
// smem: Q 16K + 2 stages x (K 16K + V 16K) = 80K.
// ---------------------------------------------------------------------------
__global__ void __launch_bounds__(256)
fa_kernel(const __half* __restrict__ q_,
          const __half* __restrict__ k_,
          const __half* __restrict__ vt_,
          const __nv_bfloat16* __restrict__ maskb,
          __half* __restrict__ z_)
{
    constexpr int QH = 0;
    constexpr int ST0 = 16384, STB = 32768;
    constexpr int KHo = 0, VHo = 16384;
    constexpr int NT = Sc / 128;

    extern __shared__ __align__(1024) char smem[];
    const uint32_t sbase = s2u(smem);

    const int tid  = threadIdx.x;
    const int wid  = tid >> 5;
    const int lane = tid & 31;

    const int z = blockIdx.y;
    const int b = z >> 4, h = z & 15;
    const int m0 = blockIdx.x * 128;

    const __half* Qp = q_  + ((size_t)(b * Sc + m0)) * Dc + h * DHc;
    const __half* Kp = k_  + (size_t)b * Sc * Dc + h * DHc;
    const __half* Vp = vt_ + ((size_t)b * Dc + h * DHc) * Sc;

    #pragma unroll
    for (int i = 0; i < 4; i++) {
        const int e = tid + i * 256;
        const int row = e >> 3, c16 = e & 7;
        const uint32_t off = SWZ(row * 128 + c16 * 16);
        CPA16(sbase + QH + off, Qp + (size_t)row * Dc + c16 * 8);
    }
    auto load_kv = [&](int kt, int s) {
        const uint32_t s0 = sbase + ST0 + s * STB;
        #pragma unroll
        for (int i = 0; i < 4; i++) {
            const int e = tid + i * 256;
            const int row = e >> 3, c16 = e & 7;
            const uint32_t off = SWZ(row * 128 + c16 * 16);
            CPA16(s0 + KHo + off, Kp + (size_t)(kt * 128 + row) * Dc + c16 * 8);
        }
        #pragma unroll
        for (int i = 0; i < 4; i++) {
            const int e = tid + i * 256;
            const int row = e >> 4, c16 = e & 15;
            const uint32_t off = SWZ(row * 256 + c16 * 16);
            CPA16(s0 + VHo + off, Vp + (size_t)row * Sc + kt * 128 + c16 * 8);
        }
    };
    load_kv(0, 0); CPA_COMMIT();
    load_kv(1, 1); CPA_COMMIT();

    const int a_r = lane & 15;
    const int a_k = (lane >> 4) & 1;
    const int b_r = lane & 7;
    const int b_k = (lane >> 3) & 1;
    const int b_n = (lane >> 4) & 1;
    const int qr  = lane >> 2;
    const int qc  = (lane & 3) * 2;

    float O[8][4];
    #pragma unroll
    for (int j = 0; j < 8; j++)
        #pragma unroll
        for (int e = 0; e < 4; e++) O[j][e] = 0.f;
    float pm0 = -1e30f, pm1 = -1e30f, l0 = 0.f, l1 = 0.f;

    const int row0 = m0 + wid * 16 + qr;
    const __nv_bfloat16* mrow0 = maskb + (size_t)row0 * Sc;
    const __nv_bfloat16* mrow1 = maskb + (size_t)(row0 + 8) * Sc;

    for (int kt = 0; kt < NT; kt++) {
        if (kt + 1 < NT) { CPA_WAIT(1); } else { CPA_WAIT(0); }
        __syncthreads();
        const uint32_t s0 = sbase + ST0 + (kt & 1) * STB;

        float s[16][4];
        #pragma unroll
        for (int j = 0; j < 16; j++)
            #pragma unroll
            for (int e = 0; e < 4; e++) s[j][e] = 0.f;

        #pragma unroll
        for (int ks = 0; ks < 4; ks++) {
            uint32_t ah[4];
            {
                const uint32_t off = SWZ((wid * 16 + a_r) * 128 + ks * 32 + a_k * 16);
                ldsm4(ah, sbase + QH + off);
            }
            #pragma unroll
            for (int j2 = 0; j2 < 8; j2++) {
                uint32_t bh[4];
                const uint32_t off = SWZ((j2 * 16 + b_n * 8 + b_r) * 128 + ks * 32 + b_k * 16);
                ldsm4(bh, s0 + KHo + off);
                mma16816h(s[j2 * 2],     ah, bh);
                mma16816h(s[j2 * 2 + 1], ah, bh + 2);
            }
        }

        float mx0 = -1e30f, mx1 = -1e30f;
        #pragma unroll
        for (int jn = 0; jn < 16; jn++) {
            const int col = kt * 128 + jn * 8 + qc;
            const float2 mv0 = __bfloat1622float2(
                *reinterpret_cast<const __nv_bfloat162*>(mrow0 + col));
            const float2 mv1 = __bfloat1622float2(
                *reinterpret_cast<const __nv_bfloat162*>(mrow1 + col));
            s[jn][0] += mv0.x;
            s[jn][1] += mv0.y;
            s[jn][2] += mv1.x;
            s[jn][3] += mv1.y;
            mx0 = fmaxf(mx0, fmaxf(s[jn][0], s[jn][1]));
            mx1 = fmaxf(mx1, fmaxf(s[jn][2], s[jn][3]));
        }
        mx0 = fmaxf(mx0, __shfl_xor_sync(0xffffffffu, mx0, 1));
        mx0 = fmaxf(mx0, __shfl_xor_sync(0xffffffffu, mx0, 2));
        mx1 = fmaxf(mx1, __shfl_xor_sync(0xffffffffu, mx1, 1));
        mx1 = fmaxf(mx1, __shfl_xor_sync(0xffffffffu, mx1, 2));
        const float nm0 = fmaxf(pm0, mx0), nm1 = fmaxf(pm1, mx1);
        const float sc0 = __expf(pm0 - nm0), sc1 = __expf(pm1 - nm1);
        l0 *= sc0; l1 *= sc1;
        #pragma unroll
        for (int j = 0; j < 8; j++) {
            O[j][0] *= sc0; O[j][1] *= sc0; O[j][2] *= sc1; O[j][3] *= sc1;
        }
        float sum0 = 0.f, sum1 = 0.f;
        #pragma unroll
        for (int jn = 0; jn < 16; jn++) {
            s[jn][0] = __expf(s[jn][0] - nm0);
            s[jn][1] = __expf(s[jn][1] - nm0);
            s[jn][2] = __expf(s[jn][2] - nm1);
            s[jn][3] = __expf(s[jn][3] - nm1);
            sum0 += s[jn][0] + s[jn][1];
            sum1 += s[jn][2] + s[jn][3];
        }
        sum0 += __shfl_xor_sync(0xffffffffu, sum0, 1);
        sum0 += __shfl_xor_sync(0xffffffffu, sum0, 2);
        sum1 += __shfl_xor_sync(0xffffffffu, sum1, 1);
        sum1 += __shfl_xor_sync(0xffffffffu, sum1, 2);
        l0 += sum0; l1 += sum1;
        pm0 = nm0; pm1 = nm1;

        #pragma unroll
        for (int ks2 = 0; ks2 < 8; ks2++) {
            uint32_t ph[4];
            ph[0] = packh2(s[2 * ks2][0],     s[2 * ks2][1]);
            ph[1] = packh2(s[2 * ks2][2],     s[2 * ks2][3]);
            ph[2] = packh2(s[2 * ks2 + 1][0], s[2 * ks2 + 1][1]);
            ph[3] = packh2(s[2 * ks2 + 1][2], s[2 * ks2 + 1][3]);
            #pragma unroll
            for (int j2 = 0; j2 < 4; j2++) {
                uint32_t vh2[4];
                const uint32_t off = SWZ((j2 * 16 + b_n * 8 + b_r) * 256 + ks2 * 32 + b_k * 16);
                ldsm4(vh2, s0 + VHo + off);
                mma16816h(O[j2 * 2],     ph, vh2);
                mma16816h(O[j2 * 2 + 1], ph, vh2 + 2);
            }
        }

        __syncthreads();
        if (kt + 2 < NT) { load_kv(kt + 2, kt & 1); CPA_COMMIT(); }
    }

    const float inv0 = 1.0f / l0, inv1 = 1.0f / l1;
    const size_t r0 = (size_t)(b * Sc + row0) * Dc + h * DHc;
    const size_t r1 = r0 + 8 * Dc;
    #pragma unroll
    for (int jn = 0; jn < 8; jn++) {
        const int n = jn * 8 + qc;
        *reinterpret_cast<uint32_t*>(z_ + r0 + n) = packh2(O[jn][0] * inv0, O[jn][1] * inv0);
        *reinterpret_cast<uint32_t*>(z_ + r1 + n) = packh2(O[jn][2] * inv1, O[jn][3] * inv1);
    }
}

// ---------------------------------------------------------------------------
// Elementwise helpers
// ---------------------------------------------------------------------------
__global__ void __launch_bounds__(256)
cvt_h_kernel(const float* __restrict__ x, __half* __restrict__ h, long long n)
{
    const long long i = ((long long)blockIdx.x * 256 + threadIdx.x) * 4;
    if (i >= n) return;
    const float4 v = *reinterpret_cast<const float4*>(x + i);
    uint32_t* hp = reinterpret_cast<uint32_t*>(h + i);
    hp[0] = packh2(v.x, v.y); hp[1] = packh2(v.z, v.w);
}

__global__ void __launch_bounds__(256)
maskbf_kernel(const float* __restrict__ m, __nv_bfloat16* __restrict__ o, long long n)
{
    const long long i = ((long long)blockIdx.x * 256 + threadIdx.x) * 4;
    if (i >= n) return;
    const float4 v = *reinterpret_cast<const float4*>(m + i);
    uint32_t* op = reinterpret_cast<uint32_t*>(o + i);
    op[0] = packbf2(v.x, v.y); op[1] = packbf2(v.z, v.w);
}

// transpose fp32 [R, C] -> fp16 [C, R] (weights)
__global__ void __launch_bounds__(256)
tsplit_h_kernel(const float* __restrict__ in, __half* __restrict__ oh, int R, int Ccols)
{
    __shared__ float t[32][33];
    const int c0 = blockIdx.x * 32, r0 = blockIdx.y * 32;
    const int tx = threadIdx.x & 31, ty = threadIdx.x >> 5;
    #pragma unroll
    for (int i = 0; i < 32; i += 8)
        t[ty + i][tx] = in[(size_t)(r0 + ty + i) * Ccols + c0 + tx];
    __syncthreads();
    #pragma unroll
    for (int i = 0; i < 32; i += 8)
        oh[(size_t)(c0 + ty + i) * R + r0 + tx] = __float2half_rn(t[tx][ty + i]);
}

// ---------------------------------------------------------------------------
// LayerNorm (+ residual); SPLIT writes single fp16 side-output
// ---------------------------------------------------------------------------
template <bool ADD_FIRST, bool SPLIT>
__global__ void __launch_bounds__(256)
ln_kernel(const float* __restrict__ a, const float* __restrict__ r,
          const float* __restrict__ g, const float* __restrict__ be,
          float* __restrict__ out, __half* __restrict__ oh)
{
    __shared__ float rs[8], rs2[8];
    const size_t base = (size_t)blockIdx.x * Dc;
    const int tid = threadIdx.x;
    float v[4];
    float s = 0.f, s2 = 0.f;
    #pragma unroll
    for (int j = 0; j < 4; j++) {
        const int c = tid + j * 256;
        float t = a[base + c];
        if (ADD_FIRST) t += r[base + c];
        v[j] = t; s += t; s2 += t * t;
    }
    #pragma unroll
    for (int o = 16; o; o >>= 1) {
        s  += __shfl_xor_sync(0xffffffffu, s, o);
        s2 += __shfl_xor_sync(0xffffffffu, s2, o);
    }
    if ((tid & 31) == 0) { rs[tid >> 5] = s; rs2[tid >> 5] = s2; }
    __syncthreads();
    if (tid == 0) {
        float t = 0.f, t2 = 0.f;
        for (int i = 0; i < 8; i++) { t += rs[i]; t2 += rs2[i]; }
        rs[0] = t; rs2[0] = t2;
    }
    __syncthreads();
    const float mu   = rs[0] * (1.0f / Dc);
    const float var  = rs2[0] * (1.0f / Dc) - mu * mu;
    const float rstd = rsqrtf(var + LN_EPS);
    #pragma unroll
    for (int j = 0; j < 4; j++) {
        const int c = tid + j * 256;
        float o = (v[j] - mu) * rstd * g[c] + be[c];
        if (!ADD_FIRST) o += r[base + c];
        out[base + c] = o;
        if (SPLIT) oh[base + c] = __float2half_rn(o);
    }
}

// ---------------------------------------------------------------------------
// Launch
// ---------------------------------------------------------------------------
extern "C" void kernel_launch(void* const* d_in, const int* in_sizes, int n_in,
                              void* d_out, int out_size)
{
    (void)in_sizes; (void)n_in; (void)out_size;

    const float* q    = (const float*)d_in[0];
    const float* k    = (const float*)d_in[1];
    const float* v    = (const float*)d_in[2];
    const float* mask = (const float*)d_in[4];
    const float* Wq   = (const float*)d_in[5];
    const float* Wk   = (const float*)d_in[6];
    const float* Wv   = (const float*)d_in[7];
    const float* Wd   = (const float*)d_in[8];
    const float* W1   = (const float*)d_in[9];
    const float* b1   = (const float*)d_in[10];
    const float* W2   = (const float*)d_in[11];
    const float* b2   = (const float*)d_in[12];
    const float* g1   = (const float*)d_in[13];
    const float* be1  = (const float*)d_in[14];
    const float* g2   = (const float*)d_in[15];
    const float* be2  = (const float*)d_in[16];
    float* out = (float*)d_out;

    float *zd, *x;
    cudaGetSymbolAddress((void**)&zd, g_zd);
    cudaGetSymbolAddress((void**)&x,  g_x);

    __nv_bfloat16 *maskb;
    __half *qi16,*ki16,*vi16,*wq16,*wk16,*wv16,*wd16,*w1h16,*w2h16;
    __half *qp16,*kp16,*vt16,*z16,*x16,*f116;
    cudaGetSymbolAddress((void**)&maskb, g_maskb);
    cudaGetSymbolAddress((void**)&qi16, g_qi16);
    cudaGetSymbolAddress((void**)&ki16, g_ki16);
    cudaGetSymbolAddress((void**)&vi16, g_vi16);
    cudaGetSymbolAddress((void**)&wq16, g_wq16); cudaGetSymbolAddress((void**)&wk16, g_wk16);
    cudaGetSymbolAddress((void**)&wv16, g_wv16); cudaGetSymbolAddress((void**)&wd16, g_wd16);
    cudaGetSymbolAddress((void**)&w1h16, g_w1h16); cudaGetSymbolAddress((void**)&w2h16, g_w2h16);
    cudaGetSymbolAddress((void**)&qp16, g_qp16);
    cudaGetSymbolAddress((void**)&kp16, g_kp16); cudaGetSymbolAddress((void**)&vt16, g_vt16);
    cudaGetSymbolAddress((void**)&z16, g_z16);
    cudaGetSymbolAddress((void**)&x16, g_x16);
    cudaGetSymbolAddress((void**)&f116, g_f116);

    constexpr int SMEM_1  = 2 * 32768;          //  65536 (GEMM)
    constexpr int SMEM_FA = 16384 + 2 * 32768;  //  81920 (FA)
    cudaFuncSetAttribute(hmma_gemm_h<0>, cudaFuncAttributeMaxDynamicSharedMemorySize, SMEM_1);
    cudaFuncSetAttribute(hmma_gemm_h<1>, cudaFuncAttributeMaxDynamicSharedMemorySize, SMEM_1);
    cudaFuncSetAttribute(hmma_gemm_h<2>, cudaFuncAttributeMaxDynamicSharedMemorySize, SMEM_1);
    cudaFuncSetAttribute(hmma_gemm_h<6>, cudaFuncAttributeMaxDynamicSharedMemorySize, SMEM_1);
    cudaFuncSetAttribute(hmma_gemm_h<7>, cudaFuncAttributeMaxDynamicSharedMemorySize, SMEM_1);
    cudaFuncSetAttribute(hmma_gemm_h<8>, cudaFuncAttributeMaxDynamicSharedMemorySize, SMEM_1);
    cudaFuncSetAttribute(fa_kernel, cudaFuncAttributeMaxDynamicSharedMemorySize, SMEM_FA);

    const dim3 b256(256);

    // ---- weight transpose (fp16) ----
    tsplit_h_kernel<<<dim3(32, 32, 1),  b256>>>(Wq, wq16, Dc, Dc);
    tsplit_h_kernel<<<dim3(32, 32, 1),  b256>>>(Wk, wk16, Dc, Dc);
    tsplit_h_kernel<<<dim3(32, 32, 1),  b256>>>(Wv, wv16, Dc, Dc);
    tsplit_h_kernel<<<dim3(32, 32, 1),  b256>>>(Wd, wd16, Dc, Dc);
    tsplit_h_kernel<<<dim3(128, 32, 1), b256>>>(W1, w1h16, Dc, FFc);
    tsplit_h_kernel<<<dim3(32, 128, 1), b256>>>(W2, w2h16, FFc, Dc);

    // ---- mask -> bf16 ----
    maskbf_kernel<<<(unsigned)((long long)Sc * Sc / 1024), b256>>>(
        mask, maskb, (long long)Sc * Sc);

    // ---- input converts (fp16) ----
    const long long nBD = (long long)BS * Dc;
    cvt_h_kernel<<<(unsigned)(nBD / 1024), b256>>>(q, qi16, nBD);
    cvt_h_kernel<<<(unsigned)(nBD / 1024), b256>>>(k, ki16, nBD);
    cvt_h_kernel<<<(unsigned)(nBD / 1024), b256>>>(v, vi16, nBD);

    // ---- QKV projections ----
    hmma_gemm_h<8><<<dim3(8, 32, 1), b256, SMEM_1>>>(     // Q: x0.125
        qi16, Dc, wq16, Dc, nullptr, qp16, Dc, Dc, nullptr);
    hmma_gemm_h<6><<<dim3(8, 32, 1), b256, SMEM_1>>>(     // K
        ki16, Dc, wk16, Dc, nullptr, kp16, Dc, Dc, nullptr);
    hmma_gemm_h<7><<<dim3(8, 32, 1), b256, SMEM_1>>>(     // V: transposed out
        vi16, Dc, wv16, Dc, nullptr, vt16, 0, Dc, nullptr);

    // ---- fused flash attention -> z (single fp16) ----
    fa_kernel<<<dim3(Sc / 128, Bc * Hc), b256, SMEM_FA>>>(
        qp16, kp16, vt16, maskb, z16);

    // ---- zd = z @ Wd ----
    hmma_gemm_h<0><<<dim3(8, 32, 1), b256, SMEM_1>>>(
        z16, Dc, wd16, Dc, zd, nullptr, Dc, Dc, nullptr);

    // ---- x = LN(zd)*g1 + be1 + q  (+ fp16 out) ----
    ln_kernel<false, true><<<BS, b256>>>(zd, q, g1, be1, x, x16);

    // ---- FFN ----
    hmma_gemm_h<2><<<dim3(32, 32, 1), b256, SMEM_1>>>(
        x16, Dc, w1h16, Dc, nullptr, f116, FFc, Dc, b1);
    hmma_gemm_h<1><<<dim3(8, 32, 1), b256, SMEM_1>>>(
        f116, FFc, w2h16, FFc, zd, nullptr, Dc, FFc, b2);

    // ---- out = LN(ff2 + x)*g2 + be2 ----
    ln_kernel<true, false><<<BS, b256>>>(zd, x, g2, be2, out, nullptr);
}